// round 10
// baseline (speedup 1.0000x reference)
#include <cuda_runtime.h>
#include <cuda_bf16.h>
#include <math.h>
#include <stdint.h>

#define BROWS 16384
#define HDIM  512
#define KDIM1 1024   // I + H
#define NDIM1 2048   // 4*H
#define LN_EPS 1e-5f

// ---------------- scratch (device globals; allocation-free rule) -----------
__device__ float g_cell[(size_t)BROWS * HDIM];
__device__ float g_og  [(size_t)BROWS * HDIM];
__device__ __nv_bfloat16 g_Ahi[(size_t)BROWS * KDIM1];
__device__ __nv_bfloat16 g_Alo[(size_t)BROWS * KDIM1];
__device__ __nv_bfloat16 g_Whi[(size_t)NDIM1 * KDIM1];   // gate-interleaved rows: 4h+gate
__device__ __nv_bfloat16 g_Wlo[(size_t)NDIM1 * KDIM1];
__device__ __nv_bfloat16 g_Shi[(size_t)BROWS * HDIM];
__device__ __nv_bfloat16 g_Slo[(size_t)BROWS * HDIM];
__device__ __nv_bfloat16 g_Phi[(size_t)HDIM * HDIM];
__device__ __nv_bfloat16 g_Plo[(size_t)HDIM * HDIM];

// ---------------- helpers ---------------------------------------------------
__device__ __forceinline__ uint32_t smem_u32(const void* p) {
    uint32_t a;
    asm("{ .reg .u64 t; cvta.to.shared.u64 t, %1; cvt.u32.u64 %0, t; }" : "=r"(a) : "l"(p));
    return a;
}
__device__ __forceinline__ void cp16(uint32_t s, const void* g) {
    asm volatile("cp.async.cg.shared.global [%0], [%1], 16;" :: "r"(s), "l"(g));
}
#define CP_COMMIT() asm volatile("cp.async.commit_group;" ::: "memory")
#define CP_WAIT(n)  asm volatile("cp.async.wait_group %0;" :: "n"(n) : "memory")

__device__ __forceinline__ void ldsm4(uint32_t* r, uint32_t addr) {
    asm volatile("ldmatrix.sync.aligned.m8n8.x4.shared.b16 {%0,%1,%2,%3}, [%4];"
                 : "=r"(r[0]), "=r"(r[1]), "=r"(r[2]), "=r"(r[3]) : "r"(addr));
}
__device__ __forceinline__ void mma16816(float* d, const uint32_t* a, uint32_t b0, uint32_t b1) {
    asm volatile(
        "mma.sync.aligned.m16n8k16.row.col.f32.bf16.bf16.f32 "
        "{%0,%1,%2,%3}, {%4,%5,%6,%7}, {%8,%9}, {%0,%1,%2,%3};"
        : "+f"(d[0]), "+f"(d[1]), "+f"(d[2]), "+f"(d[3])
        : "r"(a[0]), "r"(a[1]), "r"(a[2]), "r"(a[3]), "r"(b0), "r"(b1));
}
__device__ __forceinline__ float sigmoidf_(float x) { return 1.0f / (1.0f + expf(-x)); }

// smem tile: ROWS x 32 bf16 (64B/row), 16B-chunk swizzle: c ^= (row>>1)&3
__device__ __forceinline__ uint32_t swadr(uint32_t base, int row, int chunk) {
    return base + row * 64 + ((chunk ^ ((row >> 1) & 3)) << 4);
}

template <int ROWS>
__device__ __forceinline__ void load_tile(uint32_t sbase, const __nv_bfloat16* __restrict__ g,
                                          int row0, int koff, int K, int tid)
{
#pragma unroll
    for (int it = 0; it < ROWS / 64; it++) {
        int l = tid + it * 256;
        int r = l >> 2;
        int c = l & 3;
        cp16(swadr(sbase, r, c), g + (size_t)(row0 + r) * K + koff + c * 8);
    }
}

// ---------------------------------------------------------------------------
// Split-bf16 GEMM via mma.sync, 3-stage cp.async pipeline.
// C[BM,128] tile = A[M,K] @ B[N,K]^T ;  D += Ahi*Bhi + Ahi*Blo + Alo*Bhi
// 256 threads = 8 warps (2x4), warp tile (BM/2)x32, K-chunk 32.
// Warp-parity staggered term order to break the post-barrier LSU/tensor convoy.
// MODE 0 (BM=128): W gate-interleaved; epilogue computes cell + sigmoid(o).
// MODE 1 (BM=64): plain -> Cout (float2 stores).
// ---------------------------------------------------------------------------
template <int MODE, int BM>
__global__ __launch_bounds__(256, 2)
void gemm_mma(const __nv_bfloat16* __restrict__ Ahi, const __nv_bfloat16* __restrict__ Alo,
              const __nv_bfloat16* __restrict__ Bhi, const __nv_bfloat16* __restrict__ Blo,
              const float* __restrict__ bias, const float* __restrict__ c_prev,
              float* __restrict__ Cout, int K)
{
    constexpr int IM    = BM / 32;            // i-iterations per warp
    constexpr int ATILE = BM * 64;            // bytes per A sub-tile
    constexpr int BTILE = 128 * 64;           // bytes per B sub-tile
    constexpr int T_ALO = ATILE;
    constexpr int T_BHI = 2 * ATILE;
    constexpr int T_BLO = 2 * ATILE + BTILE;
    constexpr int STAGE = 2 * ATILE + 2 * BTILE;

    extern __shared__ char smem[];
    const uint32_t sb = smem_u32(smem);
    const int tid  = threadIdx.x;
    const int wid  = tid >> 5;
    const int lane = tid & 31;
    const int bm = blockIdx.y * BM;
    const int bn = blockIdx.x * 128;
    const int wm = (wid >> 2) * (BM / 2);
    const int wn = (wid & 3) * 32;
    const int nch = K / 32;

    const int lg = lane >> 3;
    const int lr = lane & 7;

    float acc[IM][4][4];
#pragma unroll
    for (int i = 0; i < IM; i++)
#pragma unroll
        for (int j = 0; j < 4; j++)
#pragma unroll
            for (int e = 0; e < 4; e++) acc[i][j][e] = 0.0f;

    // prologue: stages 0 and 1
#pragma unroll
    for (int p = 0; p < 2; p++) {
        uint32_t st = sb + p * STAGE;
        int ko = p * 32;
        load_tile<BM >(st,          Ahi, bm, ko, K, tid);
        load_tile<BM >(st + T_ALO,  Alo, bm, ko, K, tid);
        load_tile<128>(st + T_BHI,  Bhi, bn, ko, K, tid);
        load_tile<128>(st + T_BLO,  Blo, bn, ko, K, tid);
        CP_COMMIT();
    }

    int cur_s = 0, nxt_s = 2;
    for (int c = 0; c < nch; c++) {
        const uint32_t cur = sb + cur_s * STAGE;
        CP_WAIT(1);
        __syncthreads();
        if (c + 2 < nch) {
            const uint32_t nxt = sb + nxt_s * STAGE;
            int ko = (c + 2) * 32;
            load_tile<BM >(nxt,          Ahi, bm, ko, K, tid);
            load_tile<BM >(nxt + T_ALO,  Alo, bm, ko, K, tid);
            load_tile<128>(nxt + T_BHI,  Bhi, bn, ko, K, tid);
            load_tile<128>(nxt + T_BLO,  Blo, bn, ko, K, tid);
            CP_COMMIT();
        } else {
            CP_COMMIT();
        }

#pragma unroll
        for (int ka = 0; ka < 2; ka++) {
            const int kc = ka * 2;
            const int arow_off = lr + (lg & 1) * 8;
            const int achk     = kc + (lg >> 1);
            const int brow_off = lr + (lg >> 1) * 8;
            const int bchk     = kc + (lg & 1);

            uint32_t ah[IM][4], al[IM][4], bh[2][4], bl[2][4];

            if ((wid & 1) == 0) {
                // even warps: hi*hi -> hi*lo -> lo*hi
#pragma unroll
                for (int i = 0; i < IM; i++)
                    ldsm4(ah[i], swadr(cur, wm + i * 16 + arow_off, achk));
#pragma unroll
                for (int j = 0; j < 2; j++)
                    ldsm4(bh[j], swadr(cur + T_BHI, wn + j * 16 + brow_off, bchk));
#pragma unroll
                for (int i = 0; i < IM; i++)
#pragma unroll
                    for (int j = 0; j < 2; j++) {
                        mma16816(acc[i][2 * j + 0], ah[i], bh[j][0], bh[j][1]);
                        mma16816(acc[i][2 * j + 1], ah[i], bh[j][2], bh[j][3]);
                    }
#pragma unroll
                for (int j = 0; j < 2; j++)
                    ldsm4(bl[j], swadr(cur + T_BLO, wn + j * 16 + brow_off, bchk));
#pragma unroll
                for (int i = 0; i < IM; i++)
#pragma unroll
                    for (int j = 0; j < 2; j++) {
                        mma16816(acc[i][2 * j + 0], ah[i], bl[j][0], bl[j][1]);
                        mma16816(acc[i][2 * j + 1], ah[i], bl[j][2], bl[j][3]);
                    }
#pragma unroll
                for (int i = 0; i < IM; i++)
                    ldsm4(al[i], swadr(cur + T_ALO, wm + i * 16 + arow_off, achk));
#pragma unroll
                for (int i = 0; i < IM; i++)
#pragma unroll
                    for (int j = 0; j < 2; j++) {
                        mma16816(acc[i][2 * j + 0], al[i], bh[j][0], bh[j][1]);
                        mma16816(acc[i][2 * j + 1], al[i], bh[j][2], bh[j][3]);
                    }
            } else {
                // odd warps: lo*hi -> hi*hi -> hi*lo
#pragma unroll
                for (int i = 0; i < IM; i++)
                    ldsm4(al[i], swadr(cur + T_ALO, wm + i * 16 + arow_off, achk));
#pragma unroll
                for (int j = 0; j < 2; j++)
                    ldsm4(bh[j], swadr(cur + T_BHI, wn + j * 16 + brow_off, bchk));
#pragma unroll
                for (int i = 0; i < IM; i++)
#pragma unroll
                    for (int j = 0; j < 2; j++) {
                        mma16816(acc[i][2 * j + 0], al[i], bh[j][0], bh[j][1]);
                        mma16816(acc[i][2 * j + 1], al[i], bh[j][2], bh[j][3]);
                    }
#pragma unroll
                for (int i = 0; i < IM; i++)
                    ldsm4(ah[i], swadr(cur, wm + i * 16 + arow_off, achk));
#pragma unroll
                for (int i = 0; i < IM; i++)
#pragma unroll
                    for (int j = 0; j < 2; j++) {
                        mma16816(acc[i][2 * j + 0], ah[i], bh[j][0], bh[j][1]);
                        mma16816(acc[i][2 * j + 1], ah[i], bh[j][2], bh[j][3]);
                    }
#pragma unroll
                for (int j = 0; j < 2; j++)
                    ldsm4(bl[j], swadr(cur + T_BLO, wn + j * 16 + brow_off, bchk));
#pragma unroll
                for (int i = 0; i < IM; i++)
#pragma unroll
                    for (int j = 0; j < 2; j++) {
                        mma16816(acc[i][2 * j + 0], ah[i], bl[j][0], bl[j][1]);
                        mma16816(acc[i][2 * j + 1], ah[i], bl[j][2], bl[j][3]);
                    }
            }
        }
        cur_s = (cur_s == 2) ? 0 : cur_s + 1;
        nxt_s = (nxt_s == 2) ? 0 : nxt_s + 1;
    }

    // ---------------- epilogue ---------------------------------------------
    const int er = lane >> 2;
    const int ec = (lane & 3) * 2;
    const bool isIF = ((lane & 1) == 0);
#pragma unroll
    for (int i = 0; i < IM; i++) {
#pragma unroll
        for (int j = 0; j < 4; j++) {
#pragma unroll
            for (int half = 0; half < 2; half++) {
                int grow = bm + wm + i * 16 + er + half * 8;
                int gcol = bn + wn + j * 8 + ec;
                float v0 = acc[i][j][half * 2 + 0];
                float v1 = acc[i][j][half * 2 + 1];
                if (MODE == 0) {
                    int h     = gcol >> 2;
                    int gate0 = gcol & 3;                 // 0 (i) or 2 (g)
                    v0 += bias[gate0 * HDIM + h];
                    v1 += bias[(gate0 + 1) * HDIM + h];
                    float a0 = (gate0 == 2) ? tanhf(v0) : sigmoidf_(v0);
                    float a1 = sigmoidf_(v1);
                    float p0 = __shfl_xor_sync(0xffffffffu, a0, 1);
                    __shfl_xor_sync(0xffffffffu, a1, 1);
                    size_t idx = (size_t)grow * HDIM + h;
                    if (isIF) {
                        g_cell[idx] = a1 * c_prev[idx] + a0 * p0;
                    } else {
                        g_og[idx] = a1;
                    }
                } else {
                    *reinterpret_cast<float2*>(&Cout[(size_t)grow * HDIM + gcol]) =
                        make_float2(v0, v1);
                }
            }
        }
    }
}

// ---------------------------------------------------------------------------
// fp32 -> bf16 hi/lo split conversions
// ---------------------------------------------------------------------------
__device__ __forceinline__ void split1(float v, __nv_bfloat16* hi, __nv_bfloat16* lo) {
    __nv_bfloat16 h = __float2bfloat16(v);
    *hi = h;
    *lo = __float2bfloat16(v - __bfloat162float(h));
}

__global__ __launch_bounds__(256)
void conv_A(const float* __restrict__ x, const float* __restrict__ h)
{
    size_t i = ((size_t)blockIdx.x * blockDim.x + threadIdx.x) * 4;
    int row = (int)(i >> 10), col = (int)(i & 1023);
    const float* src = (col < 512) ? (x + (size_t)row * 512 + col)
                                   : (h + (size_t)row * 512 + (col - 512));
    float4 v = *reinterpret_cast<const float4*>(src);
    split1(v.x, &g_Ahi[i + 0], &g_Alo[i + 0]);
    split1(v.y, &g_Ahi[i + 1], &g_Alo[i + 1]);
    split1(v.z, &g_Ahi[i + 2], &g_Alo[i + 2]);
    split1(v.w, &g_Ahi[i + 3], &g_Alo[i + 3]);
}

// PERM: scatter old row r -> new row 4*(r%512) + (r/512)  (gate interleave)
template <bool PERM>
__global__ __launch_bounds__(256)
void conv_W(const float* __restrict__ src, __nv_bfloat16* __restrict__ hi,
            __nv_bfloat16* __restrict__ lo, int K, int n4)
{
    int i = blockIdx.x * blockDim.x + threadIdx.x;
    if (i >= n4) return;
    float4 v = reinterpret_cast<const float4*>(src)[i];
    size_t e = (size_t)i * 4;
    int r = (int)(e / K), col = (int)(e % K);
    int nr = PERM ? ((r & 511) * 4 + (r >> 9)) : r;
    size_t b = (size_t)nr * K + col;
    split1(v.x, &hi[b + 0], &lo[b + 0]);
    split1(v.y, &hi[b + 1], &lo[b + 1]);
    split1(v.z, &hi[b + 2], &lo[b + 2]);
    split1(v.w, &hi[b + 3], &lo[b + 3]);
}

// ---------------------------------------------------------------------------
// LayerNorm: one warp per row (8 rows/block), shfl-only reduction.
// ---------------------------------------------------------------------------
__global__ __launch_bounds__(256)
void ln_kernel(const float* __restrict__ gamma,
               const float* __restrict__ beta,
               float* __restrict__ out_cell)
{
    const int warp = threadIdx.x >> 5;
    const int lane = threadIdx.x & 31;
    const int b = blockIdx.x * 8 + warp;
    const size_t rowbase = (size_t)b * HDIM;

    float4 v[4];
#pragma unroll
    for (int q = 0; q < 4; q++)
        v[q] = *reinterpret_cast<const float4*>(&g_cell[rowbase + (q * 32 + lane) * 4]);

    float sum = 0.f, sq = 0.f;
#pragma unroll
    for (int q = 0; q < 4; q++) {
        sum += v[q].x + v[q].y + v[q].z + v[q].w;
        sq  += v[q].x * v[q].x + v[q].y * v[q].y + v[q].z * v[q].z + v[q].w * v[q].w;
    }
#pragma unroll
    for (int o = 16; o > 0; o >>= 1) {
        sum += __shfl_xor_sync(0xffffffffu, sum, o);
        sq  += __shfl_xor_sync(0xffffffffu, sq, o);
    }
    float mu  = sum * (1.0f / HDIM);
    float var = sq * (1.0f / HDIM) - mu * mu;
    float inv = rsqrtf(var + LN_EPS);

#pragma unroll
    for (int q = 0; q < 4; q++) {
        int h0 = (q * 32 + lane) * 4;
        float4 gm = *reinterpret_cast<const float4*>(&gamma[h0]);
        float4 bt = *reinterpret_cast<const float4*>(&beta[h0]);
        float4 og = *reinterpret_cast<const float4*>(&g_og[rowbase + h0]);
        float4 cn;
        cn.x = (v[q].x - mu) * inv * gm.x + bt.x;
        cn.y = (v[q].y - mu) * inv * gm.y + bt.y;
        cn.z = (v[q].z - mu) * inv * gm.z + bt.z;
        cn.w = (v[q].w - mu) * inv * gm.w + bt.w;
        *reinterpret_cast<float4*>(&out_cell[rowbase + h0]) = cn;
        float s0 = og.x * tanhf(cn.x);
        float s1 = og.y * tanhf(cn.y);
        float s2 = og.z * tanhf(cn.z);
        float s3 = og.w * tanhf(cn.w);
        __nv_bfloat16 hi[4], lo[4];
        split1(s0, &hi[0], &lo[0]);
        split1(s1, &hi[1], &lo[1]);
        split1(s2, &hi[2], &lo[2]);
        split1(s3, &hi[3], &lo[3]);
        *reinterpret_cast<uint64_t*>(&g_Shi[rowbase + h0]) = *reinterpret_cast<uint64_t*>(hi);
        *reinterpret_cast<uint64_t*>(&g_Slo[rowbase + h0]) = *reinterpret_cast<uint64_t*>(lo);
    }
}

// ---------------------------------------------------------------------------
extern "C" void kernel_launch(void* const* d_in, const int* in_sizes, int n_in,
                              void* d_out, int out_size)
{
    const float* x      = (const float*)d_in[0];
    const float* h_prev = (const float*)d_in[1];
    const float* c_prev = (const float*)d_in[2];
    const float* W      = (const float*)d_in[3];
    const float* b      = (const float*)d_in[4];
    const float* gamma  = (const float*)d_in[5];
    const float* beta   = (const float*)d_in[6];
    const float* Wp     = (const float*)d_in[7];
    float* out = (float*)d_out;                       // [out | cell]
    float* out_cell = out + (size_t)BROWS * HDIM;

    constexpr int SMEM1 = 3 * (2 * 128 * 64 + 2 * 128 * 64);   // BM=128: 96KB
    constexpr int SMEM2 = 3 * (2 * 64 * 64 + 2 * 128 * 64);    // BM=64:  72KB
    cudaFuncSetAttribute(gemm_mma<0, 128>, cudaFuncAttributeMaxDynamicSharedMemorySize, SMEM1);
    cudaFuncSetAttribute(gemm_mma<1, 64>,  cudaFuncAttributeMaxDynamicSharedMemorySize, SMEM2);

    __nv_bfloat16 *pAhi, *pAlo, *pWhi, *pWlo, *pShi, *pSlo, *pPhi, *pPlo;
    cudaGetSymbolAddress((void**)&pAhi, g_Ahi);
    cudaGetSymbolAddress((void**)&pAlo, g_Alo);
    cudaGetSymbolAddress((void**)&pWhi, g_Whi);
    cudaGetSymbolAddress((void**)&pWlo, g_Wlo);
    cudaGetSymbolAddress((void**)&pShi, g_Shi);
    cudaGetSymbolAddress((void**)&pSlo, g_Slo);
    cudaGetSymbolAddress((void**)&pPhi, g_Phi);
    cudaGetSymbolAddress((void**)&pPlo, g_Plo);

    // fp32 -> bf16 splits (W gate-interleaved)
    conv_A<<<(BROWS * KDIM1 / 4) / 256, 256>>>(x, h_prev);
    conv_W<true ><<<(NDIM1 * KDIM1 / 4 + 255) / 256, 256>>>(W,  pWhi, pWlo, KDIM1, NDIM1 * KDIM1 / 4);
    conv_W<false><<<(HDIM * HDIM / 4 + 255) / 256, 256>>>(Wp, pPhi, pPlo, HDIM,  HDIM * HDIM / 4);

    // GEMM1: gates + fused bias/activation/cell -> g_cell, g_og
    gemm_mma<0, 128><<<dim3(NDIM1 / 128, BROWS / 128), 256, SMEM1>>>(
        pAhi, pAlo, pWhi, pWlo, b, c_prev, nullptr, KDIM1);

    // LayerNorm + s (bf16 split), warp-per-row
    ln_kernel<<<BROWS / 8, 256>>>(gamma, beta, out_cell);

    // GEMM2: out = s @ Wp^T   (BM=64 -> 1024 CTAs, smaller tail)
    gemm_mma<1, 64><<<dim3(HDIM / 128, BROWS / 64), 256, SMEM2>>>(
        pShi, pSlo, pPhi, pPlo, nullptr, nullptr, out, HDIM);
}

// round 11
// speedup vs baseline: 1.3171x; 1.3171x over previous
#include <cuda_runtime.h>
#include <cuda_fp16.h>
#include <math.h>
#include <stdint.h>

#define BROWS 16384
#define HDIM  512
#define KDIM1 1024   // I + H
#define NDIM1 2048   // 4*H
#define LN_EPS 1e-5f

// ---------------- scratch (device globals; allocation-free rule) -----------
__device__ float g_cell[(size_t)BROWS * HDIM];
__device__ float g_og  [(size_t)BROWS * HDIM];
__device__ __half g_A  [(size_t)BROWS * KDIM1];            // fp16 activations (single)
__device__ __half g_Whi[(size_t)NDIM1 * KDIM1];            // gate-interleaved rows: 4h+gate
__device__ __half g_Wlo[(size_t)NDIM1 * KDIM1];
__device__ __half g_Shi[(size_t)BROWS * HDIM];
__device__ __half g_Slo[(size_t)BROWS * HDIM];
__device__ __half g_Phi[(size_t)HDIM * HDIM];
__device__ __half g_Plo[(size_t)HDIM * HDIM];

// ---------------- helpers ---------------------------------------------------
__device__ __forceinline__ uint32_t smem_u32(const void* p) {
    uint32_t a;
    asm("{ .reg .u64 t; cvta.to.shared.u64 t, %1; cvt.u32.u64 %0, t; }" : "=r"(a) : "l"(p));
    return a;
}
__device__ __forceinline__ void cp16(uint32_t s, const void* g) {
    asm volatile("cp.async.cg.shared.global [%0], [%1], 16;" :: "r"(s), "l"(g));
}
#define CP_COMMIT() asm volatile("cp.async.commit_group;" ::: "memory")
#define CP_WAIT(n)  asm volatile("cp.async.wait_group %0;" :: "n"(n) : "memory")

__device__ __forceinline__ void ldsm4(uint32_t* r, uint32_t addr) {
    asm volatile("ldmatrix.sync.aligned.m8n8.x4.shared.b16 {%0,%1,%2,%3}, [%4];"
                 : "=r"(r[0]), "=r"(r[1]), "=r"(r[2]), "=r"(r[3]) : "r"(addr));
}
__device__ __forceinline__ void mma16816(float* d, const uint32_t* a, uint32_t b0, uint32_t b1) {
    asm volatile(
        "mma.sync.aligned.m16n8k16.row.col.f32.f16.f16.f32 "
        "{%0,%1,%2,%3}, {%4,%5,%6,%7}, {%8,%9}, {%0,%1,%2,%3};"
        : "+f"(d[0]), "+f"(d[1]), "+f"(d[2]), "+f"(d[3])
        : "r"(a[0]), "r"(a[1]), "r"(a[2]), "r"(a[3]), "r"(b0), "r"(b1));
}
__device__ __forceinline__ float sigmoidf_(float x) { return 1.0f / (1.0f + expf(-x)); }

// smem tile: ROWS x 32 fp16 (64B/row), 16B-chunk swizzle: c ^= (row>>1)&3
__device__ __forceinline__ uint32_t swadr(uint32_t base, int row, int chunk) {
    return base + row * 64 + ((chunk ^ ((row >> 1) & 3)) << 4);
}

template <int ROWS>
__device__ __forceinline__ void load_tile(uint32_t sbase, const __half* __restrict__ g,
                                          int row0, int koff, int K, int tid)
{
#pragma unroll
    for (int it = 0; it < ROWS / 64; it++) {
        int l = tid + it * 256;
        int r = l >> 2;
        int c = l & 3;
        cp16(swadr(sbase, r, c), g + (size_t)(row0 + r) * K + koff + c * 8);
    }
}

// ---------------------------------------------------------------------------
// fp16 GEMM via mma.sync, 3-stage cp.async pipeline, K-chunk 32.
// MODE 0 (BM=128): 2 products, A single fp16, B=W split hi/lo:
//     D = A*Whi + A*Wlo      (error: A quantization only, ~2^-12)
//   W gate-interleaved; epilogue computes cell + sigmoid(o) directly.
// MODE 1 (BM=64): 3 products, A split hi/lo, B split hi/lo:
//     D = Ahi*Bhi + Ahi*Blo + Alo*Bhi      -> plain Cout (float2 stores)
// 256 threads = 8 warps (2x4), warp tile (BM/2)x32.
// ---------------------------------------------------------------------------
template <int MODE, int BM>
__global__ __launch_bounds__(256, 2)
void gemm_mma(const __half* __restrict__ Aop, const __half* __restrict__ Alo,
              const __half* __restrict__ Bhi, const __half* __restrict__ Blo,
              const float* __restrict__ bias, const float* __restrict__ c_prev,
              float* __restrict__ Cout, int K)
{
    constexpr int IM    = BM / 32;
    constexpr int ATILE = BM * 64;
    constexpr int BTILE = 128 * 64;
    // MODE 0: [A | BH | BL]   MODE 1: [AH | AL | BH | BL]
    constexpr int NA    = (MODE == 0) ? 1 : 2;
    constexpr int T_AL  = ATILE;                 // MODE 1 only
    constexpr int T_BH  = NA * ATILE;
    constexpr int T_BL  = NA * ATILE + BTILE;
    constexpr int STAGE = NA * ATILE + 2 * BTILE;

    extern __shared__ char smem[];
    const uint32_t sb = smem_u32(smem);
    const int tid  = threadIdx.x;
    const int wid  = tid >> 5;
    const int lane = tid & 31;
    const int bm = blockIdx.y * BM;
    const int bn = blockIdx.x * 128;
    const int wm = (wid >> 2) * (BM / 2);
    const int wn = (wid & 3) * 32;
    const int nch = K / 32;

    const int lg = lane >> 3;
    const int lr = lane & 7;

    float acc[IM][4][4];
#pragma unroll
    for (int i = 0; i < IM; i++)
#pragma unroll
        for (int j = 0; j < 4; j++)
#pragma unroll
            for (int e = 0; e < 4; e++) acc[i][j][e] = 0.0f;

    // prologue: stages 0 and 1
#pragma unroll
    for (int p = 0; p < 2; p++) {
        uint32_t st = sb + p * STAGE;
        int ko = p * 32;
        load_tile<BM >(st,        Aop, bm, ko, K, tid);
        if (MODE == 1) load_tile<BM>(st + T_AL, Alo, bm, ko, K, tid);
        load_tile<128>(st + T_BH, Bhi, bn, ko, K, tid);
        load_tile<128>(st + T_BL, Blo, bn, ko, K, tid);
        CP_COMMIT();
    }

    int cur_s = 0, nxt_s = 2;
    for (int c = 0; c < nch; c++) {
        const uint32_t cur = sb + cur_s * STAGE;
        CP_WAIT(1);
        __syncthreads();
        if (c + 2 < nch) {
            const uint32_t nxt = sb + nxt_s * STAGE;
            int ko = (c + 2) * 32;
            load_tile<BM >(nxt,        Aop, bm, ko, K, tid);
            if (MODE == 1) load_tile<BM>(nxt + T_AL, Alo, bm, ko, K, tid);
            load_tile<128>(nxt + T_BH, Bhi, bn, ko, K, tid);
            load_tile<128>(nxt + T_BL, Blo, bn, ko, K, tid);
            CP_COMMIT();
        } else {
            CP_COMMIT();
        }

#pragma unroll
        for (int ka = 0; ka < 2; ka++) {
            const int kc = ka * 2;
            const int arow_off = lr + (lg & 1) * 8;
            const int achk     = kc + (lg >> 1);
            const int brow_off = lr + (lg >> 1) * 8;
            const int bchk     = kc + (lg & 1);

            uint32_t ah[IM][4], bh[2][4], bl[2][4];
#pragma unroll
            for (int i = 0; i < IM; i++)
                ldsm4(ah[i], swadr(cur, wm + i * 16 + arow_off, achk));
#pragma unroll
            for (int j = 0; j < 2; j++)
                ldsm4(bh[j], swadr(cur + T_BH, wn + j * 16 + brow_off, bchk));

            // A(hi) * Bhi
#pragma unroll
            for (int i = 0; i < IM; i++)
#pragma unroll
                for (int j = 0; j < 2; j++) {
                    mma16816(acc[i][2 * j + 0], ah[i], bh[j][0], bh[j][1]);
                    mma16816(acc[i][2 * j + 1], ah[i], bh[j][2], bh[j][3]);
                }

            // A(hi) * Blo
#pragma unroll
            for (int j = 0; j < 2; j++)
                ldsm4(bl[j], swadr(cur + T_BL, wn + j * 16 + brow_off, bchk));
#pragma unroll
            for (int i = 0; i < IM; i++)
#pragma unroll
                for (int j = 0; j < 2; j++) {
                    mma16816(acc[i][2 * j + 0], ah[i], bl[j][0], bl[j][1]);
                    mma16816(acc[i][2 * j + 1], ah[i], bl[j][2], bl[j][3]);
                }

            if (MODE == 1) {
                // Alo * Bhi (third product)
                uint32_t al[IM][4];
#pragma unroll
                for (int i = 0; i < IM; i++)
                    ldsm4(al[i], swadr(cur + T_AL, wm + i * 16 + arow_off, achk));
#pragma unroll
                for (int i = 0; i < IM; i++)
#pragma unroll
                    for (int j = 0; j < 2; j++) {
                        mma16816(acc[i][2 * j + 0], al[i], bh[j][0], bh[j][1]);
                        mma16816(acc[i][2 * j + 1], al[i], bh[j][2], bh[j][3]);
                    }
            }
        }
        cur_s = (cur_s == 2) ? 0 : cur_s + 1;
        nxt_s = (nxt_s == 2) ? 0 : nxt_s + 1;
    }

    // ---------------- epilogue ---------------------------------------------
    const int er = lane >> 2;
    const int ec = (lane & 3) * 2;
    const bool isIF = ((lane & 1) == 0);
#pragma unroll
    for (int i = 0; i < IM; i++) {
#pragma unroll
        for (int j = 0; j < 4; j++) {
#pragma unroll
            for (int half = 0; half < 2; half++) {
                int grow = bm + wm + i * 16 + er + half * 8;
                int gcol = bn + wn + j * 8 + ec;
                float v0 = acc[i][j][half * 2 + 0];
                float v1 = acc[i][j][half * 2 + 1];
                if (MODE == 0) {
                    int h     = gcol >> 2;
                    int gate0 = gcol & 3;                 // 0 (i) or 2 (g)
                    v0 += bias[gate0 * HDIM + h];
                    v1 += bias[(gate0 + 1) * HDIM + h];
                    float a0 = (gate0 == 2) ? tanhf(v0) : sigmoidf_(v0);
                    float a1 = sigmoidf_(v1);
                    float p0 = __shfl_xor_sync(0xffffffffu, a0, 1);
                    __shfl_xor_sync(0xffffffffu, a1, 1);
                    size_t idx = (size_t)grow * HDIM + h;
                    if (isIF) {
                        g_cell[idx] = a1 * c_prev[idx] + a0 * p0;  // f*c_prev + i*tanh(g)
                    } else {
                        g_og[idx] = a1;                            // sigmoid(o)
                    }
                } else {
                    *reinterpret_cast<float2*>(&Cout[(size_t)grow * HDIM + gcol]) =
                        make_float2(v0, v1);
                }
            }
        }
    }
}

// ---------------------------------------------------------------------------
// fp32 -> fp16 conversions (single + hi/lo split)
// ---------------------------------------------------------------------------
__device__ __forceinline__ void split1h(float v, __half* hi, __half* lo) {
    __half h = __float2half_rn(v);
    *hi = h;
    *lo = __float2half_rn(v - __half2float(h));
}

__global__ __launch_bounds__(256)
void conv_A(const float* __restrict__ x, const float* __restrict__ h)
{
    size_t i = ((size_t)blockIdx.x * blockDim.x + threadIdx.x) * 4;
    int row = (int)(i >> 10), col = (int)(i & 1023);
    const float* src = (col < 512) ? (x + (size_t)row * 512 + col)
                                   : (h + (size_t)row * 512 + (col - 512));
    float4 v = *reinterpret_cast<const float4*>(src);
    g_A[i + 0] = __float2half_rn(v.x);
    g_A[i + 1] = __float2half_rn(v.y);
    g_A[i + 2] = __float2half_rn(v.z);
    g_A[i + 3] = __float2half_rn(v.w);
}

// PERM: scatter old row r -> new row 4*(r%512) + (r/512)  (gate interleave)
template <bool PERM>
__global__ __launch_bounds__(256)
void conv_W(const float* __restrict__ src, __half* __restrict__ hi,
            __half* __restrict__ lo, int K, int n4)
{
    int i = blockIdx.x * blockDim.x + threadIdx.x;
    if (i >= n4) return;
    float4 v = reinterpret_cast<const float4*>(src)[i];
    size_t e = (size_t)i * 4;
    int r = (int)(e / K), col = (int)(e % K);
    int nr = PERM ? ((r & 511) * 4 + (r >> 9)) : r;
    size_t b = (size_t)nr * K + col;
    split1h(v.x, &hi[b + 0], &lo[b + 0]);
    split1h(v.y, &hi[b + 1], &lo[b + 1]);
    split1h(v.z, &hi[b + 2], &lo[b + 2]);
    split1h(v.w, &hi[b + 3], &lo[b + 3]);
}

// ---------------------------------------------------------------------------
// LayerNorm: one warp per row (8 rows/block), shfl-only reduction.
// s = sigmoid(o) * tanh(cell_ln) -> fp16 hi/lo split (for 3-product GEMM2).
// ---------------------------------------------------------------------------
__global__ __launch_bounds__(256)
void ln_kernel(const float* __restrict__ gamma,
               const float* __restrict__ beta,
               float* __restrict__ out_cell)
{
    const int warp = threadIdx.x >> 5;
    const int lane = threadIdx.x & 31;
    const int b = blockIdx.x * 8 + warp;
    const size_t rowbase = (size_t)b * HDIM;

    float4 v[4];
#pragma unroll
    for (int q = 0; q < 4; q++)
        v[q] = *reinterpret_cast<const float4*>(&g_cell[rowbase + (q * 32 + lane) * 4]);

    float sum = 0.f, sq = 0.f;
#pragma unroll
    for (int q = 0; q < 4; q++) {
        sum += v[q].x + v[q].y + v[q].z + v[q].w;
        sq  += v[q].x * v[q].x + v[q].y * v[q].y + v[q].z * v[q].z + v[q].w * v[q].w;
    }
#pragma unroll
    for (int o = 16; o > 0; o >>= 1) {
        sum += __shfl_xor_sync(0xffffffffu, sum, o);
        sq  += __shfl_xor_sync(0xffffffffu, sq, o);
    }
    float mu  = sum * (1.0f / HDIM);
    float var = sq * (1.0f / HDIM) - mu * mu;
    float inv = rsqrtf(var + LN_EPS);

#pragma unroll
    for (int q = 0; q < 4; q++) {
        int h0 = (q * 32 + lane) * 4;
        float4 gm = *reinterpret_cast<const float4*>(&gamma[h0]);
        float4 bt = *reinterpret_cast<const float4*>(&beta[h0]);
        float4 og = *reinterpret_cast<const float4*>(&g_og[rowbase + h0]);
        float4 cn;
        cn.x = (v[q].x - mu) * inv * gm.x + bt.x;
        cn.y = (v[q].y - mu) * inv * gm.y + bt.y;
        cn.z = (v[q].z - mu) * inv * gm.z + bt.z;
        cn.w = (v[q].w - mu) * inv * gm.w + bt.w;
        *reinterpret_cast<float4*>(&out_cell[rowbase + h0]) = cn;
        float s0 = og.x * tanhf(cn.x);
        float s1 = og.y * tanhf(cn.y);
        float s2 = og.z * tanhf(cn.z);
        float s3 = og.w * tanhf(cn.w);
        __half hi[4], lo[4];
        split1h(s0, &hi[0], &lo[0]);
        split1h(s1, &hi[1], &lo[1]);
        split1h(s2, &hi[2], &lo[2]);
        split1h(s3, &hi[3], &lo[3]);
        *reinterpret_cast<uint64_t*>(&g_Shi[rowbase + h0]) = *reinterpret_cast<uint64_t*>(hi);
        *reinterpret_cast<uint64_t*>(&g_Slo[rowbase + h0]) = *reinterpret_cast<uint64_t*>(lo);
    }
}

// ---------------------------------------------------------------------------
extern "C" void kernel_launch(void* const* d_in, const int* in_sizes, int n_in,
                              void* d_out, int out_size)
{
    const float* x      = (const float*)d_in[0];
    const float* h_prev = (const float*)d_in[1];
    const float* c_prev = (const float*)d_in[2];
    const float* W      = (const float*)d_in[3];
    const float* b      = (const float*)d_in[4];
    const float* gamma  = (const float*)d_in[5];
    const float* beta   = (const float*)d_in[6];
    const float* Wp     = (const float*)d_in[7];
    float* out = (float*)d_out;                       // [out | cell]
    float* out_cell = out + (size_t)BROWS * HDIM;

    constexpr int SMEM1 = 3 * (1 * 128 * 64 + 2 * 128 * 64);   // MODE0 BM=128: 72KB
    constexpr int SMEM2 = 3 * (2 * 64 * 64 + 2 * 128 * 64);    // MODE1 BM=64:  72KB
    cudaFuncSetAttribute(gemm_mma<0, 128>, cudaFuncAttributeMaxDynamicSharedMemorySize, SMEM1);
    cudaFuncSetAttribute(gemm_mma<1, 64>,  cudaFuncAttributeMaxDynamicSharedMemorySize, SMEM2);

    __half *pA, *pWhi, *pWlo, *pShi, *pSlo, *pPhi, *pPlo;
    cudaGetSymbolAddress((void**)&pA,   g_A);
    cudaGetSymbolAddress((void**)&pWhi, g_Whi);
    cudaGetSymbolAddress((void**)&pWlo, g_Wlo);
    cudaGetSymbolAddress((void**)&pShi, g_Shi);
    cudaGetSymbolAddress((void**)&pSlo, g_Slo);
    cudaGetSymbolAddress((void**)&pPhi, g_Phi);
    cudaGetSymbolAddress((void**)&pPlo, g_Plo);

    // fp32 -> fp16 conversions (W gate-interleaved + split; A single)
    conv_A<<<(BROWS * KDIM1 / 4) / 256, 256>>>(x, h_prev);
    conv_W<true ><<<(NDIM1 * KDIM1 / 4 + 255) / 256, 256>>>(W,  pWhi, pWlo, KDIM1, NDIM1 * KDIM1 / 4);
    conv_W<false><<<(HDIM * HDIM / 4 + 255) / 256, 256>>>(Wp, pPhi, pPlo, HDIM,  HDIM * HDIM / 4);

    // GEMM1 (2 products): gates + fused bias/activation/cell -> g_cell, g_og
    gemm_mma<0, 128><<<dim3(NDIM1 / 128, BROWS / 128), 256, SMEM1>>>(
        pA, nullptr, pWhi, pWlo, b, c_prev, nullptr, KDIM1);

    // LayerNorm + s (fp16 split), warp-per-row
    ln_kernel<<<BROWS / 8, 256>>>(gamma, beta, out_cell);

    // GEMM2 (3 products): out = s @ Wp^T
    gemm_mma<1, 64><<<dim3(HDIM / 128, BROWS / 64), 256, SMEM2>>>(
        pShi, pSlo, pPhi, pPlo, nullptr, nullptr, out, HDIM);
}

// round 13
// speedup vs baseline: 1.5701x; 1.1921x over previous
#include <cuda_runtime.h>
#include <cuda_fp16.h>
#include <math.h>
#include <stdint.h>

#define BROWS 16384
#define HDIM  512
#define KDIM1 1024   // I + H
#define NDIM1 2048   // 4*H
#define LN_EPS 1e-5f

// ---------------- scratch (device globals; allocation-free rule) -----------
__device__ float g_cell[(size_t)BROWS * HDIM];
__device__ float g_og  [(size_t)BROWS * HDIM];
__device__ __half g_A  [(size_t)BROWS * KDIM1];   // fp16 activations (single)
__device__ __half g_Whi[(size_t)NDIM1 * KDIM1];   // gate-interleaved rows: 4h+gate
__device__ __half g_Wlo[(size_t)NDIM1 * KDIM1];
__device__ __half g_S  [(size_t)BROWS * HDIM];    // s = o*tanh(cell), single fp16
__device__ __half g_Phi[(size_t)HDIM * HDIM];
__device__ __half g_Plo[(size_t)HDIM * HDIM];

// ---------------- helpers ---------------------------------------------------
__device__ __forceinline__ uint32_t smem_u32(const void* p) {
    uint32_t a;
    asm("{ .reg .u64 t; cvta.to.shared.u64 t, %1; cvt.u32.u64 %0, t; }" : "=r"(a) : "l"(p));
    return a;
}
__device__ __forceinline__ void cp16(uint32_t s, const void* g) {
    asm volatile("cp.async.cg.shared.global [%0], [%1], 16;" :: "r"(s), "l"(g));
}
#define CP_COMMIT() asm volatile("cp.async.commit_group;" ::: "memory")
#define CP_WAIT(n)  asm volatile("cp.async.wait_group %0;" :: "n"(n) : "memory")

__device__ __forceinline__ void ldsm4(uint32_t* r, uint32_t addr) {
    asm volatile("ldmatrix.sync.aligned.m8n8.x4.shared.b16 {%0,%1,%2,%3}, [%4];"
                 : "=r"(r[0]), "=r"(r[1]), "=r"(r[2]), "=r"(r[3]) : "r"(addr));
}
__device__ __forceinline__ void mma16816(float* d, const uint32_t* a, uint32_t b0, uint32_t b1) {
    asm volatile(
        "mma.sync.aligned.m16n8k16.row.col.f32.f16.f16.f32 "
        "{%0,%1,%2,%3}, {%4,%5,%6,%7}, {%8,%9}, {%0,%1,%2,%3};"
        : "+f"(d[0]), "+f"(d[1]), "+f"(d[2]), "+f"(d[3])
        : "r"(a[0]), "r"(a[1]), "r"(a[2]), "r"(a[3]), "r"(b0), "r"(b1));
}
// fast activations: __expf is MUFU-based, rel err ~2^-21
__device__ __forceinline__ float fsig(float x) { return __fdividef(1.0f, 1.0f + __expf(-x)); }
__device__ __forceinline__ float ftanh_(float x) { return 2.0f * fsig(2.0f * x) - 1.0f; }

// smem tile: ROWS x 64 fp16 (128B/row), 16B-chunk swizzle: c ^= row&7  (SW128)
__device__ __forceinline__ uint32_t swadr(uint32_t base, int row, int chunk) {
    return base + (row << 7) + (((chunk ^ (row & 7)) & 7) << 4);
}

template <int ROWS>
__device__ __forceinline__ void load_tile(uint32_t sbase, const __half* __restrict__ g,
                                          int row0, int koff, int K, int tid)
{
#pragma unroll
    for (int it = 0; it < ROWS / 32; it++) {
        int l = tid + it * 256;
        int r = l >> 3;               // row
        int c = l & 7;                // 16B chunk within 128B row
        cp16(swadr(sbase, r, c), g + (size_t)(row0 + r) * K + koff + c * 8);
    }
}

// ---------------------------------------------------------------------------
// fp16 2-product GEMM via mma.sync: D = A*Bhi + A*Blo
// K-chunk 64 (128B rows), 2-stage cp.async pipeline.
// SAFE ordering: CP_WAIT(0) -> __syncthreads() -> prefetch -> compute.
// (wait_group is per-thread; the barrier AFTER the wait publishes all
//  threads' completed copies before anyone reads the tile.)
// 256 threads = 8 warps (2x4), warp tile (BM/2)x32.
// MODE 0 (BM=128): W gate-interleaved; epilogue computes cell + sigmoid(o).
// MODE 1 (BM=64): plain -> Cout (float2 stores).
// ---------------------------------------------------------------------------
template <int MODE, int BM>
__global__ __launch_bounds__(256, 2)
void gemm_mma(const __half* __restrict__ Aop,
              const __half* __restrict__ Bhi, const __half* __restrict__ Blo,
              const float* __restrict__ bias, const float* __restrict__ c_prev,
              float* __restrict__ Cout, int K)
{
    constexpr int IM    = BM / 32;
    constexpr int T_BH  = BM * 128;          // bytes: A tile is BM rows x 128B
    constexpr int T_BL  = T_BH + 128 * 128;
    constexpr int STAGE = T_BL + 128 * 128;

    extern __shared__ char smem[];
    const uint32_t sb = smem_u32(smem);
    const int tid  = threadIdx.x;
    const int wid  = tid >> 5;
    const int lane = tid & 31;
    const int bm = blockIdx.y * BM;
    const int bn = blockIdx.x * 128;
    const int wm = (wid >> 2) * (BM / 2);
    const int wn = (wid & 3) * 32;
    const int nch = K / 64;

    const int lg = lane >> 3;
    const int lr = lane & 7;
    const int arow_off = lr + (lg & 1) * 8;   // + chunk lg>>1
    const int brow_off = lr + (lg >> 1) * 8;  // + chunk lg&1

    float acc[IM][4][4];
#pragma unroll
    for (int i = 0; i < IM; i++)
#pragma unroll
        for (int j = 0; j < 4; j++)
#pragma unroll
            for (int e = 0; e < 4; e++) acc[i][j][e] = 0.0f;

    // prologue: stage 0
    load_tile<BM >(sb,        Aop, bm, 0, K, tid);
    load_tile<128>(sb + T_BH, Bhi, bn, 0, K, tid);
    load_tile<128>(sb + T_BL, Blo, bn, 0, K, tid);
    CP_COMMIT();

    for (int c = 0; c < nch; c++) {
        CP_WAIT(0);                   // my copies for stage c complete
        __syncthreads();              // everyone's copies complete; compute c-1 done
        if (c + 1 < nch) {
            const uint32_t nxt = sb + ((c + 1) & 1) * STAGE;
            int ko = (c + 1) * 64;
            load_tile<BM >(nxt,        Aop, bm, ko, K, tid);
            load_tile<128>(nxt + T_BH, Bhi, bn, ko, K, tid);
            load_tile<128>(nxt + T_BL, Blo, bn, ko, K, tid);
            CP_COMMIT();
        }

        const uint32_t cur = sb + (c & 1) * STAGE;
#pragma unroll
        for (int ka = 0; ka < 4; ka++) {
            const int achk = ka * 2 + (lg >> 1);
            const int bchk = ka * 2 + (lg & 1);

            uint32_t ah[IM][4], bh[2][4], bl[2][4];
#pragma unroll
            for (int i = 0; i < IM; i++)
                ldsm4(ah[i], swadr(cur, wm + i * 16 + arow_off, achk));
#pragma unroll
            for (int j = 0; j < 2; j++)
                ldsm4(bh[j], swadr(cur + T_BH, wn + j * 16 + brow_off, bchk));

            // A * Bhi
#pragma unroll
            for (int i = 0; i < IM; i++)
#pragma unroll
                for (int j = 0; j < 2; j++) {
                    mma16816(acc[i][2 * j + 0], ah[i], bh[j][0], bh[j][1]);
                    mma16816(acc[i][2 * j + 1], ah[i], bh[j][2], bh[j][3]);
                }

            // A * Blo
#pragma unroll
            for (int j = 0; j < 2; j++)
                ldsm4(bl[j], swadr(cur + T_BL, wn + j * 16 + brow_off, bchk));
#pragma unroll
            for (int i = 0; i < IM; i++)
#pragma unroll
                for (int j = 0; j < 2; j++) {
                    mma16816(acc[i][2 * j + 0], ah[i], bl[j][0], bl[j][1]);
                    mma16816(acc[i][2 * j + 1], ah[i], bl[j][2], bl[j][3]);
                }
        }
    }

    // ---------------- epilogue ---------------------------------------------
    const int er = lane >> 2;
    const int ec = (lane & 3) * 2;
    const bool isIF = ((lane & 1) == 0);

    if (MODE == 0) {
        // hoist bias + per-column indices (8 columns per thread)
        float bj0[4], bj1[4];
        int hj[4], gj[4];
#pragma unroll
        for (int j = 0; j < 4; j++) {
            int gcol = bn + wn + j * 8 + ec;
            hj[j] = gcol >> 2;
            gj[j] = gcol & 3;                 // 0 (i) or 2 (g)
            bj0[j] = bias[gj[j] * HDIM + hj[j]];
            bj1[j] = bias[(gj[j] + 1) * HDIM + hj[j]];
        }
#pragma unroll
        for (int i = 0; i < IM; i++) {
#pragma unroll
            for (int j = 0; j < 4; j++) {
#pragma unroll
                for (int half = 0; half < 2; half++) {
                    int grow = bm + wm + i * 16 + er + half * 8;
                    float v0 = acc[i][j][half * 2 + 0] + bj0[j];
                    float v1 = acc[i][j][half * 2 + 1] + bj1[j];
                    float a0 = (gj[j] == 2) ? ftanh_(v0) : fsig(v0);   // i or g
                    float a1 = fsig(v1);                               // f or o
                    float p0 = __shfl_xor_sync(0xffffffffu, a0, 1);
                    __shfl_xor_sync(0xffffffffu, a1, 1);   // keep lockstep
                    size_t idx = (size_t)grow * HDIM + hj[j];
                    if (isIF) {
                        g_cell[idx] = a1 * c_prev[idx] + a0 * p0;  // f*c_prev + i*tanh(g)
                    } else {
                        g_og[idx] = a1;                            // sigmoid(o)
                    }
                }
            }
        }
    } else {
#pragma unroll
        for (int i = 0; i < IM; i++) {
#pragma unroll
            for (int j = 0; j < 4; j++) {
#pragma unroll
                for (int half = 0; half < 2; half++) {
                    int grow = bm + wm + i * 16 + er + half * 8;
                    int gcol = bn + wn + j * 8 + ec;
                    *reinterpret_cast<float2*>(&Cout[(size_t)grow * HDIM + gcol]) =
                        make_float2(acc[i][j][half * 2 + 0], acc[i][j][half * 2 + 1]);
                }
            }
        }
    }
}

// ---------------------------------------------------------------------------
// fp32 -> fp16 conversions
// ---------------------------------------------------------------------------
__device__ __forceinline__ void split1h(float v, __half* hi, __half* lo) {
    __half h = __float2half_rn(v);
    *hi = h;
    *lo = __float2half_rn(v - __half2float(h));
}

__global__ __launch_bounds__(256)
void conv_A(const float* __restrict__ x, const float* __restrict__ h)
{
    size_t i = ((size_t)blockIdx.x * blockDim.x + threadIdx.x) * 4;
    int row = (int)(i >> 10), col = (int)(i & 1023);
    const float* src = (col < 512) ? (x + (size_t)row * 512 + col)
                                   : (h + (size_t)row * 512 + (col - 512));
    float4 v = *reinterpret_cast<const float4*>(src);
    g_A[i + 0] = __float2half_rn(v.x);
    g_A[i + 1] = __float2half_rn(v.y);
    g_A[i + 2] = __float2half_rn(v.z);
    g_A[i + 3] = __float2half_rn(v.w);
}

// PERM: scatter old row r -> new row 4*(r%512) + (r/512)  (gate interleave)
template <bool PERM>
__global__ __launch_bounds__(256)
void conv_W(const float* __restrict__ src, __half* __restrict__ hi,
            __half* __restrict__ lo, int K, int n4)
{
    int i = blockIdx.x * blockDim.x + threadIdx.x;
    if (i >= n4) return;
    float4 v = reinterpret_cast<const float4*>(src)[i];
    size_t e = (size_t)i * 4;
    int r = (int)(e / K), col = (int)(e % K);
    int nr = PERM ? ((r & 511) * 4 + (r >> 9)) : r;
    size_t b = (size_t)nr * K + col;
    split1h(v.x, &hi[b + 0], &lo[b + 0]);
    split1h(v.y, &hi[b + 1], &lo[b + 1]);
    split1h(v.z, &hi[b + 2], &lo[b + 2]);
    split1h(v.w, &hi[b + 3], &lo[b + 3]);
}

// ---------------------------------------------------------------------------
// LayerNorm: one warp per row (8 rows/block), shfl-only reduction.
// s = sigmoid(o) * tanh(cell_ln) -> single fp16.
// ---------------------------------------------------------------------------
__global__ __launch_bounds__(256)
void ln_kernel(const float* __restrict__ gamma,
               const float* __restrict__ beta,
               float* __restrict__ out_cell)
{
    const int warp = threadIdx.x >> 5;
    const int lane = threadIdx.x & 31;
    const int b = blockIdx.x * 8 + warp;
    const size_t rowbase = (size_t)b * HDIM;

    float4 v[4];
#pragma unroll
    for (int q = 0; q < 4; q++)
        v[q] = *reinterpret_cast<const float4*>(&g_cell[rowbase + (q * 32 + lane) * 4]);

    float sum = 0.f, sq = 0.f;
#pragma unroll
    for (int q = 0; q < 4; q++) {
        sum += v[q].x + v[q].y + v[q].z + v[q].w;
        sq  += v[q].x * v[q].x + v[q].y * v[q].y + v[q].z * v[q].z + v[q].w * v[q].w;
    }
#pragma unroll
    for (int o = 16; o > 0; o >>= 1) {
        sum += __shfl_xor_sync(0xffffffffu, sum, o);
        sq  += __shfl_xor_sync(0xffffffffu, sq, o);
    }
    float mu  = sum * (1.0f / HDIM);
    float var = sq * (1.0f / HDIM) - mu * mu;
    float inv = rsqrtf(var + LN_EPS);

#pragma unroll
    for (int q = 0; q < 4; q++) {
        int h0 = (q * 32 + lane) * 4;
        float4 gm = *reinterpret_cast<const float4*>(&gamma[h0]);
        float4 bt = *reinterpret_cast<const float4*>(&beta[h0]);
        float4 og = *reinterpret_cast<const float4*>(&g_og[rowbase + h0]);
        float4 cn;
        cn.x = (v[q].x - mu) * inv * gm.x + bt.x;
        cn.y = (v[q].y - mu) * inv * gm.y + bt.y;
        cn.z = (v[q].z - mu) * inv * gm.z + bt.z;
        cn.w = (v[q].w - mu) * inv * gm.w + bt.w;
        *reinterpret_cast<float4*>(&out_cell[rowbase + h0]) = cn;
        __half s[4];
        s[0] = __float2half_rn(og.x * ftanh_(cn.x));
        s[1] = __float2half_rn(og.y * ftanh_(cn.y));
        s[2] = __float2half_rn(og.z * ftanh_(cn.z));
        s[3] = __float2half_rn(og.w * ftanh_(cn.w));
        *reinterpret_cast<uint64_t*>(&g_S[rowbase + h0]) = *reinterpret_cast<uint64_t*>(s);
    }
}

// ---------------------------------------------------------------------------
extern "C" void kernel_launch(void* const* d_in, const int* in_sizes, int n_in,
                              void* d_out, int out_size)
{
    const float* x      = (const float*)d_in[0];
    const float* h_prev = (const float*)d_in[1];
    const float* c_prev = (const float*)d_in[2];
    const float* W      = (const float*)d_in[3];
    const float* b      = (const float*)d_in[4];
    const float* gamma  = (const float*)d_in[5];
    const float* beta   = (const float*)d_in[6];
    const float* Wp     = (const float*)d_in[7];
    float* out = (float*)d_out;                       // [out | cell]
    float* out_cell = out + (size_t)BROWS * HDIM;

    constexpr int SMEM1 = 2 * (128 * 128 + 2 * 128 * 128);   // BM=128: 96KB
    constexpr int SMEM2 = 2 * (64 * 128 + 2 * 128 * 128);    // BM=64:  80KB
    cudaFuncSetAttribute(gemm_mma<0, 128>, cudaFuncAttributeMaxDynamicSharedMemorySize, SMEM1);
    cudaFuncSetAttribute(gemm_mma<1, 64>,  cudaFuncAttributeMaxDynamicSharedMemorySize, SMEM2);

    __half *pA, *pWhi, *pWlo, *pS, *pPhi, *pPlo;
    cudaGetSymbolAddress((void**)&pA,   g_A);
    cudaGetSymbolAddress((void**)&pWhi, g_Whi);
    cudaGetSymbolAddress((void**)&pWlo, g_Wlo);
    cudaGetSymbolAddress((void**)&pS,   g_S);
    cudaGetSymbolAddress((void**)&pPhi, g_Phi);
    cudaGetSymbolAddress((void**)&pPlo, g_Plo);

    // fp32 -> fp16 conversions (W gate-interleaved + split; A single)
    conv_A<<<(BROWS * KDIM1 / 4) / 256, 256>>>(x, h_prev);
    conv_W<true ><<<(NDIM1 * KDIM1 / 4 + 255) / 256, 256>>>(W,  pWhi, pWlo, KDIM1, NDIM1 * KDIM1 / 4);
    conv_W<false><<<(HDIM * HDIM / 4 + 255) / 256, 256>>>(Wp, pPhi, pPlo, HDIM,  HDIM * HDIM / 4);

    // GEMM1 (2 products): gates + fused bias/activation/cell -> g_cell, g_og
    gemm_mma<0, 128><<<dim3(NDIM1 / 128, BROWS / 128), 256, SMEM1>>>(
        pA, pWhi, pWlo, b, c_prev, nullptr, KDIM1);

    // LayerNorm + s (single fp16), warp-per-row
    ln_kernel<<<BROWS / 8, 256>>>(gamma, beta, out_cell);

    // GEMM2 (2 products): out = s @ (Phi + Plo)^T
    gemm_mma<1, 64><<<dim3(HDIM / 128, BROWS / 64), 256, SMEM2>>>(
        pS, pPhi, pPlo, nullptr, nullptr, out, HDIM);
}

// round 14
// speedup vs baseline: 2.2003x; 1.4014x over previous
#include <cuda_runtime.h>
#include <cuda_fp16.h>
#include <math.h>
#include <stdint.h>

#define BROWS 16384
#define HDIM  512
#define KDIM1 1024   // I + H
#define NDIM1 2048   // 4*H
#define LN_EPS 1e-5f

// ---------------- scratch (device globals; allocation-free rule) -----------
__device__ float g_cell[(size_t)BROWS * HDIM];
__device__ float g_og  [(size_t)BROWS * HDIM];
__device__ __half g_A  [(size_t)BROWS * KDIM1];   // fp16 activations (single)
__device__ __half g_W  [(size_t)NDIM1 * KDIM1];   // fp16 W, gate-interleaved rows: 4h+gate
__device__ __half g_S  [(size_t)BROWS * HDIM];    // s = o*tanh(cell), single fp16
__device__ __half g_Phi[(size_t)HDIM * HDIM];
__device__ __half g_Plo[(size_t)HDIM * HDIM];

// ---------------- helpers ---------------------------------------------------
__device__ __forceinline__ uint32_t smem_u32(const void* p) {
    uint32_t a;
    asm("{ .reg .u64 t; cvta.to.shared.u64 t, %1; cvt.u32.u64 %0, t; }" : "=r"(a) : "l"(p));
    return a;
}
__device__ __forceinline__ void cp16(uint32_t s, const void* g) {
    asm volatile("cp.async.cg.shared.global [%0], [%1], 16;" :: "r"(s), "l"(g));
}
#define CP_COMMIT() asm volatile("cp.async.commit_group;" ::: "memory")
#define CP_WAIT(n)  asm volatile("cp.async.wait_group %0;" :: "n"(n) : "memory")

__device__ __forceinline__ void ldsm4(uint32_t* r, uint32_t addr) {
    asm volatile("ldmatrix.sync.aligned.m8n8.x4.shared.b16 {%0,%1,%2,%3}, [%4];"
                 : "=r"(r[0]), "=r"(r[1]), "=r"(r[2]), "=r"(r[3]) : "r"(addr));
}
__device__ __forceinline__ void mma16816(float* d, const uint32_t* a, uint32_t b0, uint32_t b1) {
    asm volatile(
        "mma.sync.aligned.m16n8k16.row.col.f32.f16.f16.f32 "
        "{%0,%1,%2,%3}, {%4,%5,%6,%7}, {%8,%9}, {%0,%1,%2,%3};"
        : "+f"(d[0]), "+f"(d[1]), "+f"(d[2]), "+f"(d[3])
        : "r"(a[0]), "r"(a[1]), "r"(a[2]), "r"(a[3]), "r"(b0), "r"(b1));
}
// fast activations: __expf is MUFU-based, rel err ~2^-21
__device__ __forceinline__ float fsig(float x) { return __fdividef(1.0f, 1.0f + __expf(-x)); }
__device__ __forceinline__ float ftanh_(float x) { return 2.0f * fsig(2.0f * x) - 1.0f; }

// smem tile: ROWS x 64 fp16 (128B/row), 16B-chunk swizzle: c ^= row&7  (SW128)
__device__ __forceinline__ uint32_t swadr(uint32_t base, int row, int chunk) {
    return base + (row << 7) + (((chunk ^ (row & 7)) & 7) << 4);
}

template <int ROWS>
__device__ __forceinline__ void load_tile(uint32_t sbase, const __half* __restrict__ g,
                                          int row0, int koff, int K, int tid)
{
#pragma unroll
    for (int it = 0; it < ROWS / 32; it++) {
        int l = tid + it * 256;
        int r = l >> 3;               // row
        int c = l & 7;                // 16B chunk within 128B row
        cp16(swadr(sbase, r, c), g + (size_t)(row0 + r) * K + koff + c * 8);
    }
}

// ---------------------------------------------------------------------------
// fp16 GEMM via mma.sync. K-chunk 64 (128B rows), 2-stage cp.async pipeline.
// SAFE ordering: CP_WAIT(0) -> __syncthreads() -> prefetch -> compute.
// MODE 0 (BM=128, 1 product): D = A @ W       (W gate-interleaved;
//          epilogue computes cell + sigmoid(o) directly)
// MODE 1 (BM=64, 2 products): D = A*Bhi + A*Blo -> plain Cout
// 256 threads = 8 warps (2x4), warp tile (BM/2)x32.
// ---------------------------------------------------------------------------
template <int MODE, int BM>
__global__ __launch_bounds__(256, 2)
void gemm_mma(const __half* __restrict__ Aop,
              const __half* __restrict__ Bhi, const __half* __restrict__ Blo,
              const float* __restrict__ bias, const float* __restrict__ c_prev,
              float* __restrict__ Cout, int K)
{
    constexpr int IM    = BM / 32;
    constexpr int NPB   = (MODE == 0) ? 1 : 2;        // B tiles per stage
    constexpr int T_BH  = BM * 128;
    constexpr int T_BL  = T_BH + 128 * 128;
    constexpr int STAGE = BM * 128 + NPB * 128 * 128;

    extern __shared__ char smem[];
    const uint32_t sb = smem_u32(smem);
    const int tid  = threadIdx.x;
    const int wid  = tid >> 5;
    const int lane = tid & 31;
    const int bm = blockIdx.y * BM;
    const int bn = blockIdx.x * 128;
    const int wm = (wid >> 2) * (BM / 2);
    const int wn = (wid & 3) * 32;
    const int nch = K / 64;

    const int lg = lane >> 3;
    const int lr = lane & 7;
    const int arow_off = lr + (lg & 1) * 8;   // + chunk lg>>1
    const int brow_off = lr + (lg >> 1) * 8;  // + chunk lg&1

    float acc[IM][4][4];
#pragma unroll
    for (int i = 0; i < IM; i++)
#pragma unroll
        for (int j = 0; j < 4; j++)
#pragma unroll
            for (int e = 0; e < 4; e++) acc[i][j][e] = 0.0f;

    // prologue: stage 0
    load_tile<BM >(sb,        Aop, bm, 0, K, tid);
    load_tile<128>(sb + T_BH, Bhi, bn, 0, K, tid);
    if (MODE == 1) load_tile<128>(sb + T_BL, Blo, bn, 0, K, tid);
    CP_COMMIT();

    for (int c = 0; c < nch; c++) {
        CP_WAIT(0);                   // my copies for stage c complete
        __syncthreads();              // everyone's copies complete; compute c-1 done
        if (c + 1 < nch) {
            const uint32_t nxt = sb + ((c + 1) & 1) * STAGE;
            int ko = (c + 1) * 64;
            load_tile<BM >(nxt,        Aop, bm, ko, K, tid);
            load_tile<128>(nxt + T_BH, Bhi, bn, ko, K, tid);
            if (MODE == 1) load_tile<128>(nxt + T_BL, Blo, bn, ko, K, tid);
            CP_COMMIT();
        }

        const uint32_t cur = sb + (c & 1) * STAGE;
#pragma unroll
        for (int ka = 0; ka < 4; ka++) {
            const int achk = ka * 2 + (lg >> 1);
            const int bchk = ka * 2 + (lg & 1);

            uint32_t ah[IM][4], bh[2][4];
#pragma unroll
            for (int i = 0; i < IM; i++)
                ldsm4(ah[i], swadr(cur, wm + i * 16 + arow_off, achk));
#pragma unroll
            for (int j = 0; j < 2; j++)
                ldsm4(bh[j], swadr(cur + T_BH, wn + j * 16 + brow_off, bchk));

            // A * Bhi
#pragma unroll
            for (int i = 0; i < IM; i++)
#pragma unroll
                for (int j = 0; j < 2; j++) {
                    mma16816(acc[i][2 * j + 0], ah[i], bh[j][0], bh[j][1]);
                    mma16816(acc[i][2 * j + 1], ah[i], bh[j][2], bh[j][3]);
                }

            if (MODE == 1) {
                // A * Blo
                uint32_t bl[2][4];
#pragma unroll
                for (int j = 0; j < 2; j++)
                    ldsm4(bl[j], swadr(cur + T_BL, wn + j * 16 + brow_off, bchk));
#pragma unroll
                for (int i = 0; i < IM; i++)
#pragma unroll
                    for (int j = 0; j < 2; j++) {
                        mma16816(acc[i][2 * j + 0], ah[i], bl[j][0], bl[j][1]);
                        mma16816(acc[i][2 * j + 1], ah[i], bl[j][2], bl[j][3]);
                    }
            }
        }
    }

    // ---------------- epilogue ---------------------------------------------
    const int er = lane >> 2;
    const int ec = (lane & 3) * 2;
    const bool isIF = ((lane & 1) == 0);

    if (MODE == 0) {
        // hoist bias + per-column indices (8 columns per thread)
        float bj0[4], bj1[4];
        int hj[4], gj[4];
#pragma unroll
        for (int j = 0; j < 4; j++) {
            int gcol = bn + wn + j * 8 + ec;
            hj[j] = gcol >> 2;
            gj[j] = gcol & 3;                 // 0 (i) or 2 (g)
            bj0[j] = bias[gj[j] * HDIM + hj[j]];
            bj1[j] = bias[(gj[j] + 1) * HDIM + hj[j]];
        }
#pragma unroll
        for (int i = 0; i < IM; i++) {
#pragma unroll
            for (int j = 0; j < 4; j++) {
#pragma unroll
                for (int half = 0; half < 2; half++) {
                    int grow = bm + wm + i * 16 + er + half * 8;
                    float v0 = acc[i][j][half * 2 + 0] + bj0[j];
                    float v1 = acc[i][j][half * 2 + 1] + bj1[j];
                    float a0 = (gj[j] == 2) ? ftanh_(v0) : fsig(v0);   // i or g
                    float a1 = fsig(v1);                               // f or o
                    float p0 = __shfl_xor_sync(0xffffffffu, a0, 1);
                    __shfl_xor_sync(0xffffffffu, a1, 1);   // keep lockstep
                    size_t idx = (size_t)grow * HDIM + hj[j];
                    if (isIF) {
                        g_cell[idx] = a1 * c_prev[idx] + a0 * p0;  // f*c_prev + i*tanh(g)
                    } else {
                        g_og[idx] = a1;                            // sigmoid(o)
                    }
                }
            }
        }
    } else {
#pragma unroll
        for (int i = 0; i < IM; i++) {
#pragma unroll
            for (int j = 0; j < 4; j++) {
#pragma unroll
                for (int half = 0; half < 2; half++) {
                    int grow = bm + wm + i * 16 + er + half * 8;
                    int gcol = bn + wn + j * 8 + ec;
                    *reinterpret_cast<float2*>(&Cout[(size_t)grow * HDIM + gcol]) =
                        make_float2(acc[i][j][half * 2 + 0], acc[i][j][half * 2 + 1]);
                }
            }
        }
    }
}

// ---------------------------------------------------------------------------
// fp32 -> fp16 conversions
// ---------------------------------------------------------------------------
__device__ __forceinline__ void split1h(float v, __half* hi, __half* lo) {
    __half h = __float2half_rn(v);
    *hi = h;
    *lo = __float2half_rn(v - __half2float(h));
}

__global__ __launch_bounds__(256)
void conv_A(const float* __restrict__ x, const float* __restrict__ h)
{
    size_t i = ((size_t)blockIdx.x * blockDim.x + threadIdx.x) * 4;
    int row = (int)(i >> 10), col = (int)(i & 1023);
    const float* src = (col < 512) ? (x + (size_t)row * 512 + col)
                                   : (h + (size_t)row * 512 + (col - 512));
    float4 v = *reinterpret_cast<const float4*>(src);
    g_A[i + 0] = __float2half_rn(v.x);
    g_A[i + 1] = __float2half_rn(v.y);
    g_A[i + 2] = __float2half_rn(v.z);
    g_A[i + 3] = __float2half_rn(v.w);
}

// W conversion: gate-interleave permutation (old row r -> 4*(r%512) + r/512),
// single fp16 output.
__global__ __launch_bounds__(256)
void conv_W1(const float* __restrict__ src, __half* __restrict__ dst, int n4)
{
    int i = blockIdx.x * blockDim.x + threadIdx.x;
    if (i >= n4) return;
    float4 v = reinterpret_cast<const float4*>(src)[i];
    size_t e = (size_t)i * 4;
    int r = (int)(e / KDIM1), col = (int)(e % KDIM1);
    int nr = (r & 511) * 4 + (r >> 9);
    size_t b = (size_t)nr * KDIM1 + col;
    dst[b + 0] = __float2half_rn(v.x);
    dst[b + 1] = __float2half_rn(v.y);
    dst[b + 2] = __float2half_rn(v.z);
    dst[b + 3] = __float2half_rn(v.w);
}

// Wp conversion: hi/lo split, no permutation.
__global__ __launch_bounds__(256)
void conv_Wp(const float* __restrict__ src, __half* __restrict__ hi,
             __half* __restrict__ lo, int n4)
{
    int i = blockIdx.x * blockDim.x + threadIdx.x;
    if (i >= n4) return;
    float4 v = reinterpret_cast<const float4*>(src)[i];
    size_t b = (size_t)i * 4;
    split1h(v.x, &hi[b + 0], &lo[b + 0]);
    split1h(v.y, &hi[b + 1], &lo[b + 1]);
    split1h(v.z, &hi[b + 2], &lo[b + 2]);
    split1h(v.w, &hi[b + 3], &lo[b + 3]);
}

// ---------------------------------------------------------------------------
// LayerNorm: one warp per row (8 rows/block), shfl-only reduction.
// s = sigmoid(o) * tanh(cell_ln) -> single fp16.
// ---------------------------------------------------------------------------
__global__ __launch_bounds__(256)
void ln_kernel(const float* __restrict__ gamma,
               const float* __restrict__ beta,
               float* __restrict__ out_cell)
{
    const int warp = threadIdx.x >> 5;
    const int lane = threadIdx.x & 31;
    const int b = blockIdx.x * 8 + warp;
    const size_t rowbase = (size_t)b * HDIM;

    float4 v[4];
#pragma unroll
    for (int q = 0; q < 4; q++)
        v[q] = *reinterpret_cast<const float4*>(&g_cell[rowbase + (q * 32 + lane) * 4]);

    float sum = 0.f, sq = 0.f;
#pragma unroll
    for (int q = 0; q < 4; q++) {
        sum += v[q].x + v[q].y + v[q].z + v[q].w;
        sq  += v[q].x * v[q].x + v[q].y * v[q].y + v[q].z * v[q].z + v[q].w * v[q].w;
    }
#pragma unroll
    for (int o = 16; o > 0; o >>= 1) {
        sum += __shfl_xor_sync(0xffffffffu, sum, o);
        sq  += __shfl_xor_sync(0xffffffffu, sq, o);
    }
    float mu  = sum * (1.0f / HDIM);
    float var = sq * (1.0f / HDIM) - mu * mu;
    float inv = rsqrtf(var + LN_EPS);

#pragma unroll
    for (int q = 0; q < 4; q++) {
        int h0 = (q * 32 + lane) * 4;
        float4 gm = *reinterpret_cast<const float4*>(&gamma[h0]);
        float4 bt = *reinterpret_cast<const float4*>(&beta[h0]);
        float4 og = *reinterpret_cast<const float4*>(&g_og[rowbase + h0]);
        float4 cn;
        cn.x = (v[q].x - mu) * inv * gm.x + bt.x;
        cn.y = (v[q].y - mu) * inv * gm.y + bt.y;
        cn.z = (v[q].z - mu) * inv * gm.z + bt.z;
        cn.w = (v[q].w - mu) * inv * gm.w + bt.w;
        *reinterpret_cast<float4*>(&out_cell[rowbase + h0]) = cn;
        __half s[4];
        s[0] = __float2half_rn(og.x * ftanh_(cn.x));
        s[1] = __float2half_rn(og.y * ftanh_(cn.y));
        s[2] = __float2half_rn(og.z * ftanh_(cn.z));
        s[3] = __float2half_rn(og.w * ftanh_(cn.w));
        *reinterpret_cast<uint64_t*>(&g_S[rowbase + h0]) = *reinterpret_cast<uint64_t*>(s);
    }
}

// ---------------------------------------------------------------------------
extern "C" void kernel_launch(void* const* d_in, const int* in_sizes, int n_in,
                              void* d_out, int out_size)
{
    const float* x      = (const float*)d_in[0];
    const float* h_prev = (const float*)d_in[1];
    const float* c_prev = (const float*)d_in[2];
    const float* W      = (const float*)d_in[3];
    const float* b      = (const float*)d_in[4];
    const float* gamma  = (const float*)d_in[5];
    const float* beta   = (const float*)d_in[6];
    const float* Wp     = (const float*)d_in[7];
    float* out = (float*)d_out;                       // [out | cell]
    float* out_cell = out + (size_t)BROWS * HDIM;

    constexpr int SMEM1 = 2 * (128 * 128 + 1 * 128 * 128);   // MODE0 BM=128: 64KB
    constexpr int SMEM2 = 2 * (64 * 128 + 2 * 128 * 128);    // MODE1 BM=64:  80KB
    cudaFuncSetAttribute(gemm_mma<0, 128>, cudaFuncAttributeMaxDynamicSharedMemorySize, SMEM1);
    cudaFuncSetAttribute(gemm_mma<1, 64>,  cudaFuncAttributeMaxDynamicSharedMemorySize, SMEM2);

    __half *pA, *pW, *pS, *pPhi, *pPlo;
    cudaGetSymbolAddress((void**)&pA,   g_A);
    cudaGetSymbolAddress((void**)&pW,   g_W);
    cudaGetSymbolAddress((void**)&pS,   g_S);
    cudaGetSymbolAddress((void**)&pPhi, g_Phi);
    cudaGetSymbolAddress((void**)&pPlo, g_Plo);

    // fp32 -> fp16 conversions
    conv_A<<<(BROWS * KDIM1 / 4) / 256, 256>>>(x, h_prev);
    conv_W1<<<(NDIM1 * KDIM1 / 4 + 255) / 256, 256>>>(W, pW, NDIM1 * KDIM1 / 4);
    conv_Wp<<<(HDIM * HDIM / 4 + 255) / 256, 256>>>(Wp, pPhi, pPlo, HDIM * HDIM / 4);

    // GEMM1 (1 product): gates + fused bias/activation/cell -> g_cell, g_og
    gemm_mma<0, 128><<<dim3(NDIM1 / 128, BROWS / 128), 256, SMEM1>>>(
        pA, pW, nullptr, b, c_prev, nullptr, KDIM1);

    // LayerNorm + s (single fp16), warp-per-row
    ln_kernel<<<BROWS / 8, 256>>>(gamma, beta, out_cell);

    // GEMM2 (2 products): out = s @ (Phi + Plo)^T
    gemm_mma<1, 64><<<dim3(HDIM / 128, BROWS / 64), 256, SMEM2>>>(
        pS, pPhi, pPlo, nullptr, nullptr, out, HDIM);
}

// round 15
// speedup vs baseline: 2.2007x; 1.0002x over previous
#include <cuda_runtime.h>
#include <cuda_fp16.h>
#include <math.h>
#include <stdint.h>

#define BROWS 16384
#define HDIM  512
#define KDIM1 1024   // I + H
#define NDIM1 2048   // 4*H
#define LN_EPS 1e-5f

// ---------------- scratch (device globals; allocation-free rule) -----------
__device__ float g_cell[(size_t)BROWS * HDIM];
__device__ float g_og  [(size_t)BROWS * HDIM];
__device__ __half g_A  [(size_t)BROWS * KDIM1];   // fp16 activations
__device__ __half g_W  [(size_t)NDIM1 * KDIM1];   // fp16 W, gate-interleaved rows: 4h+gate
__device__ __half g_S  [(size_t)BROWS * HDIM];    // s = o*tanh(cell)
__device__ __half g_P  [(size_t)HDIM * HDIM];     // fp16 Wp

// ---------------- helpers ---------------------------------------------------
__device__ __forceinline__ uint32_t smem_u32(const void* p) {
    uint32_t a;
    asm("{ .reg .u64 t; cvta.to.shared.u64 t, %1; cvt.u32.u64 %0, t; }" : "=r"(a) : "l"(p));
    return a;
}
__device__ __forceinline__ void cp16(uint32_t s, const void* g) {
    asm volatile("cp.async.cg.shared.global [%0], [%1], 16;" :: "r"(s), "l"(g));
}
#define CP_COMMIT() asm volatile("cp.async.commit_group;" ::: "memory")
#define CP_WAIT(n)  asm volatile("cp.async.wait_group %0;" :: "n"(n) : "memory")

__device__ __forceinline__ void ldsm4(uint32_t* r, uint32_t addr) {
    asm volatile("ldmatrix.sync.aligned.m8n8.x4.shared.b16 {%0,%1,%2,%3}, [%4];"
                 : "=r"(r[0]), "=r"(r[1]), "=r"(r[2]), "=r"(r[3]) : "r"(addr));
}
__device__ __forceinline__ void mma16816(float* d, const uint32_t* a, uint32_t b0, uint32_t b1) {
    asm volatile(
        "mma.sync.aligned.m16n8k16.row.col.f32.f16.f16.f32 "
        "{%0,%1,%2,%3}, {%4,%5,%6,%7}, {%8,%9}, {%0,%1,%2,%3};"
        : "+f"(d[0]), "+f"(d[1]), "+f"(d[2]), "+f"(d[3])
        : "r"(a[0]), "r"(a[1]), "r"(a[2]), "r"(a[3]), "r"(b0), "r"(b1));
}
// fast activations: __expf is MUFU-based, rel err ~2^-21
__device__ __forceinline__ float fsig(float x) { return __fdividef(1.0f, 1.0f + __expf(-x)); }
__device__ __forceinline__ float ftanh_(float x) { return 2.0f * fsig(2.0f * x) - 1.0f; }

// smem tile: ROWS x 64 fp16 (128B/row), 16B-chunk swizzle: c ^= row&7  (SW128)
__device__ __forceinline__ uint32_t swadr(uint32_t base, int row, int chunk) {
    return base + (row << 7) + (((chunk ^ (row & 7)) & 7) << 4);
}

template <int ROWS>
__device__ __forceinline__ void load_tile(uint32_t sbase, const __half* __restrict__ g,
                                          int row0, int koff, int K, int tid)
{
#pragma unroll
    for (int it = 0; it < ROWS / 32; it++) {
        int l = tid + it * 256;
        int r = l >> 3;               // row
        int c = l & 7;                // 16B chunk within 128B row
        cp16(swadr(sbase, r, c), g + (size_t)(row0 + r) * K + koff + c * 8);
    }
}

// ---------------------------------------------------------------------------
// fp16 1-product GEMM via mma.sync: D = A @ B^T.
// K-chunk 64 (128B rows), 2-stage cp.async pipeline.
// SAFE ordering: CP_WAIT(0) -> __syncthreads() -> ldsm(ka0) -> prefetch ->
//                mma loop (reload frags for next ka after each mma burst).
// 256 threads = 8 warps (2x4), warp tile (BM/2)x32.
// MODE 0 (BM=128): W gate-interleaved; epilogue computes cell + sigmoid(o).
// MODE 1 (BM=64): plain -> Cout (float2 stores).
// ---------------------------------------------------------------------------
template <int MODE, int BM>
__global__ __launch_bounds__(256, 2)
void gemm_mma(const __half* __restrict__ Aop, const __half* __restrict__ Bop,
              const float* __restrict__ bias, const float* __restrict__ c_prev,
              float* __restrict__ Cout, int K)
{
    constexpr int IM    = BM / 32;
    constexpr int T_BH  = BM * 128;
    constexpr int STAGE = BM * 128 + 128 * 128;

    extern __shared__ char smem[];
    const uint32_t sb = smem_u32(smem);
    const int tid  = threadIdx.x;
    const int wid  = tid >> 5;
    const int lane = tid & 31;
    const int bm = blockIdx.y * BM;
    const int bn = blockIdx.x * 128;
    const int wm = (wid >> 2) * (BM / 2);
    const int wn = (wid & 3) * 32;
    const int nch = K / 64;

    const int lg = lane >> 3;
    const int lr = lane & 7;
    const int arow_off = lr + (lg & 1) * 8;   // + chunk lg>>1
    const int brow_off = lr + (lg >> 1) * 8;  // + chunk lg&1
    const int achk0 = lg >> 1;
    const int bchk0 = lg & 1;

    float acc[IM][4][4];
#pragma unroll
    for (int i = 0; i < IM; i++)
#pragma unroll
        for (int j = 0; j < 4; j++)
#pragma unroll
            for (int e = 0; e < 4; e++) acc[i][j][e] = 0.0f;

    // prologue: stage 0
    load_tile<BM >(sb,        Aop, bm, 0, K, tid);
    load_tile<128>(sb + T_BH, Bop, bn, 0, K, tid);
    CP_COMMIT();

    for (int c = 0; c < nch; c++) {
        CP_WAIT(0);                   // my copies for stage c complete
        __syncthreads();              // everyone's copies complete; compute c-1 done

        const uint32_t cur = sb + (c & 1) * STAGE;

        // fragments for ka=0 (data already resident) BEFORE issuing prefetch,
        // so tensor work starts immediately and cp.async issue overlaps mma.
        uint32_t ah[IM][4], bh[2][4];
#pragma unroll
        for (int i = 0; i < IM; i++)
            ldsm4(ah[i], swadr(cur, wm + i * 16 + arow_off, achk0));
#pragma unroll
        for (int j = 0; j < 2; j++)
            ldsm4(bh[j], swadr(cur + T_BH, wn + j * 16 + brow_off, bchk0));

        if (c + 1 < nch) {
            const uint32_t nxt = sb + ((c + 1) & 1) * STAGE;
            int ko = (c + 1) * 64;
            load_tile<BM >(nxt,        Aop, bm, ko, K, tid);
            load_tile<128>(nxt + T_BH, Bop, bn, ko, K, tid);
            CP_COMMIT();
        }

#pragma unroll
        for (int ka = 0; ka < 4; ka++) {
#pragma unroll
            for (int i = 0; i < IM; i++)
#pragma unroll
                for (int j = 0; j < 2; j++) {
                    mma16816(acc[i][2 * j + 0], ah[i], bh[j][0], bh[j][1]);
                    mma16816(acc[i][2 * j + 1], ah[i], bh[j][2], bh[j][3]);
                }
            if (ka < 3) {
                const int achk = (ka + 1) * 2 + achk0;
                const int bchk = (ka + 1) * 2 + bchk0;
#pragma unroll
                for (int i = 0; i < IM; i++)
                    ldsm4(ah[i], swadr(cur, wm + i * 16 + arow_off, achk));
#pragma unroll
                for (int j = 0; j < 2; j++)
                    ldsm4(bh[j], swadr(cur + T_BH, wn + j * 16 + brow_off, bchk));
            }
        }
    }

    // ---------------- epilogue ---------------------------------------------
    const int er = lane >> 2;
    const int ec = (lane & 3) * 2;
    const bool isIF = ((lane & 1) == 0);

    if (MODE == 0) {
        // hoist bias + per-column indices (8 columns per thread)
        float bj0[4], bj1[4];
        int hj[4], gj[4];
#pragma unroll
        for (int j = 0; j < 4; j++) {
            int gcol = bn + wn + j * 8 + ec;
            hj[j] = gcol >> 2;
            gj[j] = gcol & 3;                 // 0 (i) or 2 (g)
            bj0[j] = bias[gj[j] * HDIM + hj[j]];
            bj1[j] = bias[(gj[j] + 1) * HDIM + hj[j]];
        }
#pragma unroll
        for (int i = 0; i < IM; i++) {
#pragma unroll
            for (int j = 0; j < 4; j++) {
#pragma unroll
                for (int half = 0; half < 2; half++) {
                    int grow = bm + wm + i * 16 + er + half * 8;
                    float v0 = acc[i][j][half * 2 + 0] + bj0[j];
                    float v1 = acc[i][j][half * 2 + 1] + bj1[j];
                    float a0 = (gj[j] == 2) ? ftanh_(v0) : fsig(v0);   // i or g
                    float a1 = fsig(v1);                               // f or o
                    float p0 = __shfl_xor_sync(0xffffffffu, a0, 1);
                    __shfl_xor_sync(0xffffffffu, a1, 1);   // keep lockstep
                    size_t idx = (size_t)grow * HDIM + hj[j];
                    if (isIF) {
                        g_cell[idx] = a1 * c_prev[idx] + a0 * p0;  // f*c_prev + i*tanh(g)
                    } else {
                        g_og[idx] = a1;                            // sigmoid(o)
                    }
                }
            }
        }
    } else {
#pragma unroll
        for (int i = 0; i < IM; i++) {
#pragma unroll
            for (int j = 0; j < 4; j++) {
#pragma unroll
                for (int half = 0; half < 2; half++) {
                    int grow = bm + wm + i * 16 + er + half * 8;
                    int gcol = bn + wn + j * 8 + ec;
                    *reinterpret_cast<float2*>(&Cout[(size_t)grow * HDIM + gcol]) =
                        make_float2(acc[i][j][half * 2 + 0], acc[i][j][half * 2 + 1]);
                }
            }
        }
    }
}

// ---------------------------------------------------------------------------
// fp32 -> fp16 conversions
// ---------------------------------------------------------------------------
__global__ __launch_bounds__(256)
void conv_A(const float* __restrict__ x, const float* __restrict__ h)
{
    size_t i = ((size_t)blockIdx.x * blockDim.x + threadIdx.x) * 4;
    int row = (int)(i >> 10), col = (int)(i & 1023);
    const float* src = (col < 512) ? (x + (size_t)row * 512 + col)
                                   : (h + (size_t)row * 512 + (col - 512));
    float4 v = *reinterpret_cast<const float4*>(src);
    g_A[i + 0] = __float2half_rn(v.x);
    g_A[i + 1] = __float2half_rn(v.y);
    g_A[i + 2] = __float2half_rn(v.z);
    g_A[i + 3] = __float2half_rn(v.w);
}

// PERM: gate-interleave permutation (old row r -> 4*(r%512) + r/512)
template <bool PERM>
__global__ __launch_bounds__(256)
void conv_W1(const float* __restrict__ src, __half* __restrict__ dst, int K, int n4)
{
    int i = blockIdx.x * blockDim.x + threadIdx.x;
    if (i >= n4) return;
    float4 v = reinterpret_cast<const float4*>(src)[i];
    size_t e = (size_t)i * 4;
    int r = (int)(e / K), col = (int)(e % K);
    int nr = PERM ? ((r & 511) * 4 + (r >> 9)) : r;
    size_t b = (size_t)nr * K + col;
    dst[b + 0] = __float2half_rn(v.x);
    dst[b + 1] = __float2half_rn(v.y);
    dst[b + 2] = __float2half_rn(v.z);
    dst[b + 3] = __float2half_rn(v.w);
}

// ---------------------------------------------------------------------------
// LayerNorm: one warp per row (8 rows/block), shfl-only reduction.
// s = sigmoid(o) * tanh(cell_ln) -> single fp16.
// ---------------------------------------------------------------------------
__global__ __launch_bounds__(256)
void ln_kernel(const float* __restrict__ gamma,
               const float* __restrict__ beta,
               float* __restrict__ out_cell)
{
    const int warp = threadIdx.x >> 5;
    const int lane = threadIdx.x & 31;
    const int b = blockIdx.x * 8 + warp;
    const size_t rowbase = (size_t)b * HDIM;

    float4 v[4];
#pragma unroll
    for (int q = 0; q < 4; q++)
        v[q] = *reinterpret_cast<const float4*>(&g_cell[rowbase + (q * 32 + lane) * 4]);

    float sum = 0.f, sq = 0.f;
#pragma unroll
    for (int q = 0; q < 4; q++) {
        sum += v[q].x + v[q].y + v[q].z + v[q].w;
        sq  += v[q].x * v[q].x + v[q].y * v[q].y + v[q].z * v[q].z + v[q].w * v[q].w;
    }
#pragma unroll
    for (int o = 16; o > 0; o >>= 1) {
        sum += __shfl_xor_sync(0xffffffffu, sum, o);
        sq  += __shfl_xor_sync(0xffffffffu, sq, o);
    }
    float mu  = sum * (1.0f / HDIM);
    float var = sq * (1.0f / HDIM) - mu * mu;
    float inv = rsqrtf(var + LN_EPS);

#pragma unroll
    for (int q = 0; q < 4; q++) {
        int h0 = (q * 32 + lane) * 4;
        float4 gm = *reinterpret_cast<const float4*>(&gamma[h0]);
        float4 bt = *reinterpret_cast<const float4*>(&beta[h0]);
        float4 og = *reinterpret_cast<const float4*>(&g_og[rowbase + h0]);
        float4 cn;
        cn.x = (v[q].x - mu) * inv * gm.x + bt.x;
        cn.y = (v[q].y - mu) * inv * gm.y + bt.y;
        cn.z = (v[q].z - mu) * inv * gm.z + bt.z;
        cn.w = (v[q].w - mu) * inv * gm.w + bt.w;
        *reinterpret_cast<float4*>(&out_cell[rowbase + h0]) = cn;
        __half s[4];
        s[0] = __float2half_rn(og.x * ftanh_(cn.x));
        s[1] = __float2half_rn(og.y * ftanh_(cn.y));
        s[2] = __float2half_rn(og.z * ftanh_(cn.z));
        s[3] = __float2half_rn(og.w * ftanh_(cn.w));
        *reinterpret_cast<uint64_t*>(&g_S[rowbase + h0]) = *reinterpret_cast<uint64_t*>(s);
    }
}

// ---------------------------------------------------------------------------
extern "C" void kernel_launch(void* const* d_in, const int* in_sizes, int n_in,
                              void* d_out, int out_size)
{
    const float* x      = (const float*)d_in[0];
    const float* h_prev = (const float*)d_in[1];
    const float* c_prev = (const float*)d_in[2];
    const float* W      = (const float*)d_in[3];
    const float* b      = (const float*)d_in[4];
    const float* gamma  = (const float*)d_in[5];
    const float* beta   = (const float*)d_in[6];
    const float* Wp     = (const float*)d_in[7];
    float* out = (float*)d_out;                       // [out | cell]
    float* out_cell = out + (size_t)BROWS * HDIM;

    constexpr int SMEM1 = 2 * (128 * 128 + 128 * 128);   // BM=128: 64KB
    constexpr int SMEM2 = 2 * (64 * 128 + 128 * 128);    // BM=64:  48KB
    cudaFuncSetAttribute(gemm_mma<0, 128>, cudaFuncAttributeMaxDynamicSharedMemorySize, SMEM1);
    cudaFuncSetAttribute(gemm_mma<1, 64>,  cudaFuncAttributeMaxDynamicSharedMemorySize, SMEM2);

    __half *pA, *pW, *pS, *pP;
    cudaGetSymbolAddress((void**)&pA, g_A);
    cudaGetSymbolAddress((void**)&pW, g_W);
    cudaGetSymbolAddress((void**)&pS, g_S);
    cudaGetSymbolAddress((void**)&pP, g_P);

    // fp32 -> fp16 conversions
    conv_A<<<(BROWS * KDIM1 / 4) / 256, 256>>>(x, h_prev);
    conv_W1<true ><<<(NDIM1 * KDIM1 / 4 + 255) / 256, 256>>>(W,  pW, KDIM1, NDIM1 * KDIM1 / 4);
    conv_W1<false><<<(HDIM * HDIM / 4 + 255) / 256, 256>>>(Wp, pP, HDIM,  HDIM * HDIM / 4);

    // GEMM1: gates + fused bias/activation/cell -> g_cell, g_og
    gemm_mma<0, 128><<<dim3(NDIM1 / 128, BROWS / 128), 256, SMEM1>>>(
        pA, pW, b, c_prev, nullptr, KDIM1);

    // LayerNorm + s (single fp16), warp-per-row
    ln_kernel<<<BROWS / 8, 256>>>(gamma, beta, out_cell);

    // GEMM2: out = s @ Wp^T
    gemm_mma<1, 64><<<dim3(HDIM / 128, BROWS / 64), 256, SMEM2>>>(
        pS, pP, nullptr, nullptr, out, HDIM);
}

// round 16
// speedup vs baseline: 2.3264x; 1.0571x over previous
#include <cuda_runtime.h>
#include <cuda_fp16.h>
#include <math.h>
#include <stdint.h>

#define BROWS 16384
#define HDIM  512
#define KDIM1 1024   // I + H
#define NDIM1 2048   // 4*H
#define LN_EPS 1e-5f

// ---------------- scratch (device globals; allocation-free rule) -----------
__device__ float g_cell[(size_t)BROWS * HDIM];
__device__ float g_og  [(size_t)BROWS * HDIM];
__device__ __half g_A  [(size_t)BROWS * KDIM1];   // fp16 activations
__device__ __half g_W  [(size_t)NDIM1 * KDIM1];   // fp16 W, gate-interleaved rows: 4h+gate
__device__ __half g_S  [(size_t)BROWS * HDIM];    // s = o*tanh(cell)
__device__ __half g_P  [(size_t)HDIM * HDIM];     // fp16 Wp

// ---------------- helpers ---------------------------------------------------
__device__ __forceinline__ uint32_t smem_u32(const void* p) {
    uint32_t a;
    asm("{ .reg .u64 t; cvta.to.shared.u64 t, %1; cvt.u32.u64 %0, t; }" : "=r"(a) : "l"(p));
    return a;
}
__device__ __forceinline__ void cp16(uint32_t s, const void* g) {
    asm volatile("cp.async.cg.shared.global [%0], [%1], 16;" :: "r"(s), "l"(g));
}
#define CP_COMMIT() asm volatile("cp.async.commit_group;" ::: "memory")
#define CP_WAIT(n)  asm volatile("cp.async.wait_group %0;" :: "n"(n) : "memory")

__device__ __forceinline__ void ldsm4(uint32_t* r, uint32_t addr) {
    asm volatile("ldmatrix.sync.aligned.m8n8.x4.shared.b16 {%0,%1,%2,%3}, [%4];"
                 : "=r"(r[0]), "=r"(r[1]), "=r"(r[2]), "=r"(r[3]) : "r"(addr));
}
__device__ __forceinline__ void mma16816(float* d, const uint32_t* a, uint32_t b0, uint32_t b1) {
    asm volatile(
        "mma.sync.aligned.m16n8k16.row.col.f32.f16.f16.f32 "
        "{%0,%1,%2,%3}, {%4,%5,%6,%7}, {%8,%9}, {%0,%1,%2,%3};"
        : "+f"(d[0]), "+f"(d[1]), "+f"(d[2]), "+f"(d[3])
        : "r"(a[0]), "r"(a[1]), "r"(a[2]), "r"(a[3]), "r"(b0), "r"(b1));
}
// fast activations: __expf is MUFU-based, rel err ~2^-21
__device__ __forceinline__ float fsig(float x) { return __fdividef(1.0f, 1.0f + __expf(-x)); }
__device__ __forceinline__ float ftanh_(float x) { return 2.0f * fsig(2.0f * x) - 1.0f; }

// smem tile: ROWS x 64 fp16 (128B/row), 16B-chunk swizzle: c ^= row&7  (SW128)
__device__ __forceinline__ uint32_t swadr(uint32_t base, int row, int chunk) {
    return base + (row << 7) + (((chunk ^ (row & 7)) & 7) << 4);
}

template <int ROWS>
__device__ __forceinline__ void load_tile(uint32_t sbase, const __half* __restrict__ g,
                                          int row0, int koff, int K, int tid)
{
#pragma unroll
    for (int it = 0; it < ROWS / 32; it++) {
        int l = tid + it * 256;
        int r = l >> 3;               // row
        int c = l & 7;                // 16B chunk within 128B row
        cp16(swadr(sbase, r, c), g + (size_t)(row0 + r) * K + koff + c * 8);
    }
}

// ---------------------------------------------------------------------------
// fp16 1-product GEMM via mma.sync: D = A @ B^T.
// K-chunk 64 (128B rows), 2-stage cp.async pipeline.
// R13-proven ordering: CP_WAIT(0) -> __syncthreads() -> prefetch -> ka loop
// (ldsm burst then mma burst per ka; let ptxas schedule).
// 256 threads = 8 warps (2x4), warp tile (BM/2)x32.
// MODE 0 (BM=128): W gate-interleaved; epilogue computes cell + sigmoid(o).
// MODE 1 (BM=64): plain -> Cout (float2 stores).
// ---------------------------------------------------------------------------
template <int MODE, int BM>
__global__ __launch_bounds__(256, 2)
void gemm_mma(const __half* __restrict__ Aop, const __half* __restrict__ Bop,
              const float* __restrict__ bias, const float* __restrict__ c_prev,
              float* __restrict__ Cout, int K)
{
    constexpr int IM    = BM / 32;
    constexpr int T_BH  = BM * 128;
    constexpr int STAGE = BM * 128 + 128 * 128;

    extern __shared__ char smem[];
    const uint32_t sb = smem_u32(smem);
    const int tid  = threadIdx.x;
    const int wid  = tid >> 5;
    const int lane = tid & 31;
    const int bm = blockIdx.y * BM;
    const int bn = blockIdx.x * 128;
    const int wm = (wid >> 2) * (BM / 2);
    const int wn = (wid & 3) * 32;
    const int nch = K / 64;

    const int lg = lane >> 3;
    const int lr = lane & 7;
    const int arow_off = lr + (lg & 1) * 8;   // + chunk lg>>1
    const int brow_off = lr + (lg >> 1) * 8;  // + chunk lg&1

    float acc[IM][4][4];
#pragma unroll
    for (int i = 0; i < IM; i++)
#pragma unroll
        for (int j = 0; j < 4; j++)
#pragma unroll
            for (int e = 0; e < 4; e++) acc[i][j][e] = 0.0f;

    // prologue: stage 0
    load_tile<BM >(sb,        Aop, bm, 0, K, tid);
    load_tile<128>(sb + T_BH, Bop, bn, 0, K, tid);
    CP_COMMIT();

    for (int c = 0; c < nch; c++) {
        CP_WAIT(0);                   // my copies for stage c complete
        __syncthreads();              // everyone's copies complete; compute c-1 done
        if (c + 1 < nch) {
            const uint32_t nxt = sb + ((c + 1) & 1) * STAGE;
            int ko = (c + 1) * 64;
            load_tile<BM >(nxt,        Aop, bm, ko, K, tid);
            load_tile<128>(nxt + T_BH, Bop, bn, ko, K, tid);
            CP_COMMIT();
        }

        const uint32_t cur = sb + (c & 1) * STAGE;
#pragma unroll
        for (int ka = 0; ka < 4; ka++) {
            const int achk = ka * 2 + (lg >> 1);
            const int bchk = ka * 2 + (lg & 1);

            uint32_t ah[IM][4], bh[2][4];
#pragma unroll
            for (int i = 0; i < IM; i++)
                ldsm4(ah[i], swadr(cur, wm + i * 16 + arow_off, achk));
#pragma unroll
            for (int j = 0; j < 2; j++)
                ldsm4(bh[j], swadr(cur + T_BH, wn + j * 16 + brow_off, bchk));

#pragma unroll
            for (int i = 0; i < IM; i++)
#pragma unroll
                for (int j = 0; j < 2; j++) {
                    mma16816(acc[i][2 * j + 0], ah[i], bh[j][0], bh[j][1]);
                    mma16816(acc[i][2 * j + 1], ah[i], bh[j][2], bh[j][3]);
                }
        }
    }

    // ---------------- epilogue ---------------------------------------------
    const int er = lane >> 2;
    const int ec = (lane & 3) * 2;
    const bool isIF = ((lane & 1) == 0);

    if (MODE == 0) {
        // hoist bias + per-column indices (8 columns per thread)
        float bj0[4], bj1[4];
        int hj[4], gj[4];
#pragma unroll
        for (int j = 0; j < 4; j++) {
            int gcol = bn + wn + j * 8 + ec;
            hj[j] = gcol >> 2;
            gj[j] = gcol & 3;                 // 0 (i) or 2 (g)
            bj0[j] = bias[gj[j] * HDIM + hj[j]];
            bj1[j] = bias[(gj[j] + 1) * HDIM + hj[j]];
        }
#pragma unroll
        for (int i = 0; i < IM; i++) {
#pragma unroll
            for (int j = 0; j < 4; j++) {
#pragma unroll
                for (int half = 0; half < 2; half++) {
                    int grow = bm + wm + i * 16 + er + half * 8;
                    float v0 = acc[i][j][half * 2 + 0] + bj0[j];
                    float v1 = acc[i][j][half * 2 + 1] + bj1[j];
                    float a0 = (gj[j] == 2) ? ftanh_(v0) : fsig(v0);   // i or g
                    float a1 = fsig(v1);                               // f or o
                    float p0 = __shfl_xor_sync(0xffffffffu, a0, 1);
                    __shfl_xor_sync(0xffffffffu, a1, 1);   // keep lockstep
                    size_t idx = (size_t)grow * HDIM + hj[j];
                    if (isIF) {
                        g_cell[idx] = a1 * c_prev[idx] + a0 * p0;  // f*c_prev + i*tanh(g)
                    } else {
                        g_og[idx] = a1;                            // sigmoid(o)
                    }
                }
            }
        }
    } else {
#pragma unroll
        for (int i = 0; i < IM; i++) {
#pragma unroll
            for (int j = 0; j < 4; j++) {
#pragma unroll
                for (int half = 0; half < 2; half++) {
                    int grow = bm + wm + i * 16 + er + half * 8;
                    int gcol = bn + wn + j * 8 + ec;
                    *reinterpret_cast<float2*>(&Cout[(size_t)grow * HDIM + gcol]) =
                        make_float2(acc[i][j][half * 2 + 0], acc[i][j][half * 2 + 1]);
                }
            }
        }
    }
}

// ---------------------------------------------------------------------------
// fp32 -> fp16 conversions
// ---------------------------------------------------------------------------
__global__ __launch_bounds__(256)
void conv_A(const float* __restrict__ x, const float* __restrict__ h)
{
    size_t i = ((size_t)blockIdx.x * blockDim.x + threadIdx.x) * 4;
    int row = (int)(i >> 10), col = (int)(i & 1023);
    const float* src = (col < 512) ? (x + (size_t)row * 512 + col)
                                   : (h + (size_t)row * 512 + (col - 512));
    float4 v = *reinterpret_cast<const float4*>(src);
    g_A[i + 0] = __float2half_rn(v.x);
    g_A[i + 1] = __float2half_rn(v.y);
    g_A[i + 2] = __float2half_rn(v.z);
    g_A[i + 3] = __float2half_rn(v.w);
}

// PERM: gate-interleave permutation (old row r -> 4*(r%512) + r/512)
template <bool PERM>
__global__ __launch_bounds__(256)
void conv_W1(const float* __restrict__ src, __half* __restrict__ dst, int K, int n4)
{
    int i = blockIdx.x * blockDim.x + threadIdx.x;
    if (i >= n4) return;
    float4 v = reinterpret_cast<const float4*>(src)[i];
    size_t e = (size_t)i * 4;
    int r = (int)(e / K), col = (int)(e % K);
    int nr = PERM ? ((r & 511) * 4 + (r >> 9)) : r;
    size_t b = (size_t)nr * K + col;
    dst[b + 0] = __float2half_rn(v.x);
    dst[b + 1] = __float2half_rn(v.y);
    dst[b + 2] = __float2half_rn(v.z);
    dst[b + 3] = __float2half_rn(v.w);
}

// ---------------------------------------------------------------------------
// LayerNorm: one warp per row (8 rows/block), shfl-only reduction.
// s = sigmoid(o) * tanh(cell_ln) -> single fp16.
// ---------------------------------------------------------------------------
__global__ __launch_bounds__(256)
void ln_kernel(const float* __restrict__ gamma,
               const float* __restrict__ beta,
               float* __restrict__ out_cell)
{
    const int warp = threadIdx.x >> 5;
    const int lane = threadIdx.x & 31;
    const int b = blockIdx.x * 8 + warp;
    const size_t rowbase = (size_t)b * HDIM;

    float4 v[4];
#pragma unroll
    for (int q = 0; q < 4; q++)
        v[q] = *reinterpret_cast<const float4*>(&g_cell[rowbase + (q * 32 + lane) * 4]);

    float sum = 0.f, sq = 0.f;
#pragma unroll
    for (int q = 0; q < 4; q++) {
        sum += v[q].x + v[q].y + v[q].z + v[q].w;
        sq  += v[q].x * v[q].x + v[q].y * v[q].y + v[q].z * v[q].z + v[q].w * v[q].w;
    }
#pragma unroll
    for (int o = 16; o > 0; o >>= 1) {
        sum += __shfl_xor_sync(0xffffffffu, sum, o);
        sq  += __shfl_xor_sync(0xffffffffu, sq, o);
    }
    float mu  = sum * (1.0f / HDIM);
    float var = sq * (1.0f / HDIM) - mu * mu;
    float inv = rsqrtf(var + LN_EPS);

#pragma unroll
    for (int q = 0; q < 4; q++) {
        int h0 = (q * 32 + lane) * 4;
        float4 gm = *reinterpret_cast<const float4*>(&gamma[h0]);
        float4 bt = *reinterpret_cast<const float4*>(&beta[h0]);
        float4 og = *reinterpret_cast<const float4*>(&g_og[rowbase + h0]);
        float4 cn;
        cn.x = (v[q].x - mu) * inv * gm.x + bt.x;
        cn.y = (v[q].y - mu) * inv * gm.y + bt.y;
        cn.z = (v[q].z - mu) * inv * gm.z + bt.z;
        cn.w = (v[q].w - mu) * inv * gm.w + bt.w;
        *reinterpret_cast<float4*>(&out_cell[rowbase + h0]) = cn;
        __half s[4];
        s[0] = __float2half_rn(og.x * ftanh_(cn.x));
        s[1] = __float2half_rn(og.y * ftanh_(cn.y));
        s[2] = __float2half_rn(og.z * ftanh_(cn.z));
        s[3] = __float2half_rn(og.w * ftanh_(cn.w));
        *reinterpret_cast<uint64_t*>(&g_S[rowbase + h0]) = *reinterpret_cast<uint64_t*>(s);
    }
}

// ---------------------------------------------------------------------------
extern "C" void kernel_launch(void* const* d_in, const int* in_sizes, int n_in,
                              void* d_out, int out_size)
{
    const float* x      = (const float*)d_in[0];
    const float* h_prev = (const float*)d_in[1];
    const float* c_prev = (const float*)d_in[2];
    const float* W      = (const float*)d_in[3];
    const float* b      = (const float*)d_in[4];
    const float* gamma  = (const float*)d_in[5];
    const float* beta   = (const float*)d_in[6];
    const float* Wp     = (const float*)d_in[7];
    float* out = (float*)d_out;                       // [out | cell]
    float* out_cell = out + (size_t)BROWS * HDIM;

    constexpr int SMEM1 = 2 * (128 * 128 + 128 * 128);   // BM=128: 64KB
    constexpr int SMEM2 = 2 * (64 * 128 + 128 * 128);    // BM=64:  48KB
    cudaFuncSetAttribute(gemm_mma<0, 128>, cudaFuncAttributeMaxDynamicSharedMemorySize, SMEM1);
    cudaFuncSetAttribute(gemm_mma<1, 64>,  cudaFuncAttributeMaxDynamicSharedMemorySize, SMEM2);

    __half *pA, *pW, *pS, *pP;
    cudaGetSymbolAddress((void**)&pA, g_A);
    cudaGetSymbolAddress((void**)&pW, g_W);
    cudaGetSymbolAddress((void**)&pS, g_S);
    cudaGetSymbolAddress((void**)&pP, g_P);

    // fp32 -> fp16 conversions
    conv_A<<<(BROWS * KDIM1 / 4) / 256, 256>>>(x, h_prev);
    conv_W1<true ><<<(NDIM1 * KDIM1 / 4 + 255) / 256, 256>>>(W,  pW, KDIM1, NDIM1 * KDIM1 / 4);
    conv_W1<false><<<(HDIM * HDIM / 4 + 255) / 256, 256>>>(Wp, pP, HDIM,  HDIM * HDIM / 4);

    // GEMM1: gates + fused bias/activation/cell -> g_cell, g_og
    gemm_mma<0, 128><<<dim3(NDIM1 / 128, BROWS / 128), 256, SMEM1>>>(
        pA, pW, b, c_prev, nullptr, KDIM1);

    // LayerNorm + s (single fp16), warp-per-row
    ln_kernel<<<BROWS / 8, 256>>>(gamma, beta, out_cell);

    // GEMM2: out = s @ Wp^T
    gemm_mma<1, 64><<<dim3(HDIM / 128, BROWS / 64), 256, SMEM2>>>(
        pS, pP, nullptr, nullptr, out, HDIM);
}